// round 1
// baseline (speedup 1.0000x reference)
#include <cuda_runtime.h>
#include <cstdint>
#include <math.h>

#define MAXN 50000
#define F1 128
#define F2 16

// ---------------- device scratch (no allocation allowed) ----------------
__device__ __align__(256) float g_deg [MAXN];
__device__ __align__(256) float g_dinv[MAXN];
__device__ __align__(256) float g_h1s [MAXN * F1];  // (x@W1) * dinv[row]
__device__ __align__(256) float g_acc1[MAXN * F1];  // scatter target layer 1
__device__ __align__(256) float g_h2s [MAXN * F2];  // (relu(...)@W2) * dinv[row]
__device__ __align__(256) float g_acc2[MAXN * F2];  // scatter target layer 2
__device__ int g_is64;

// ---------------- helpers ----------------
__device__ __forceinline__ long long load_idx(const void* ei, long long i, int is64) {
    if (is64) return ((const long long*)ei)[i];
    return (long long)((const int*)ei)[i];
}

__device__ __forceinline__ void red_add_v4(float* addr, float4 v) {
    asm volatile("red.global.add.v4.f32 [%0], {%1,%2,%3,%4};"
                 :: "l"(addr), "f"(v.x), "f"(v.y), "f"(v.z), "f"(v.w)
                 : "memory");
}

// ---------------- kernels ----------------

// Detect int32 vs int64 edge_index: int64-true data has all values in [0, n).
__global__ void detect_kernel(const void* ei, int n) {
    const long long* p = (const long long*)ei;
    int ok = 1;
    for (int i = 0; i < 8; i++) {
        long long v = p[i];
        if (v < 0 || v >= n) ok = 0;
    }
    g_is64 = ok;
}

__global__ void zero_kernel(int n) {
    long long stride = (long long)gridDim.x * blockDim.x;
    long long tid = (long long)blockIdx.x * blockDim.x + threadIdx.x;
    for (long long i = tid; i < (long long)n * F1; i += stride) g_acc1[i] = 0.f;
    for (long long i = tid; i < (long long)n * F2; i += stride) g_acc2[i] = 0.f;
    for (long long i = tid; i < n;                 i += stride) g_deg[i]  = 0.f;
}

__global__ void deg_kernel(const void* ei, long long E) {
    long long i = (long long)blockIdx.x * blockDim.x + threadIdx.x;
    if (i >= E) return;
    long long d = load_idx(ei, E + i, g_is64);
    atomicAdd(&g_deg[d], 1.0f);
}

__global__ void dinv_kernel(int n) {
    int i = blockIdx.x * blockDim.x + threadIdx.x;
    if (i >= n) return;
    g_dinv[i] = rsqrtf(fmaxf(g_deg[i], 1.0f));
}

// h1s = (x @ W1) * dinv[row].  BM=64 rows/block, all 128 cols, BK=32.
// 256 threads, thread tile 4 rows x 8 cols.
__global__ void gemm1_kernel(const float* __restrict__ x,
                             const float* __restrict__ W1, int n) {
    __shared__ float Xs[64][33];
    __shared__ float Ws[32][128];
    const int tid = threadIdx.x;
    const int tr = tid >> 4;        // 0..15
    const int tc = tid & 15;        // 0..15
    const int row0 = blockIdx.x * 64;

    float acc[4][8];
#pragma unroll
    for (int r = 0; r < 4; r++)
#pragma unroll
        for (int c = 0; c < 8; c++) acc[r][c] = 0.f;

    for (int k0 = 0; k0 < 128; k0 += 32) {
        // load Xs: 64x32 floats as float4 (512 float4, 2 per thread)
#pragma unroll
        for (int i = tid; i < 512; i += 256) {
            int r  = i >> 3;          // /8 float4 per row
            int c4 = i & 7;
            int grow = row0 + r;
            float4 v = make_float4(0.f, 0.f, 0.f, 0.f);
            if (grow < n)
                v = *(const float4*)&x[(long long)grow * 128 + k0 + c4 * 4];
            Xs[r][c4 * 4 + 0] = v.x;
            Xs[r][c4 * 4 + 1] = v.y;
            Xs[r][c4 * 4 + 2] = v.z;
            Xs[r][c4 * 4 + 3] = v.w;
        }
        // load Ws: 32x128 floats (1024 float4, 4 per thread)
#pragma unroll
        for (int i = tid; i < 1024; i += 256) {
            int r  = i >> 5;          // /32 float4 per row
            int c4 = i & 31;
            float4 v = *(const float4*)&W1[(long long)(k0 + r) * 128 + c4 * 4];
            *(float4*)&Ws[r][c4 * 4] = v;
        }
        __syncthreads();
#pragma unroll
        for (int kk = 0; kk < 32; kk++) {
            float a[4];
#pragma unroll
            for (int r = 0; r < 4; r++) a[r] = Xs[tr * 4 + r][kk];
            float4 w0 = *(float4*)&Ws[kk][tc * 8];
            float4 w1 = *(float4*)&Ws[kk][tc * 8 + 4];
#pragma unroll
            for (int r = 0; r < 4; r++) {
                acc[r][0] += a[r] * w0.x;  acc[r][1] += a[r] * w0.y;
                acc[r][2] += a[r] * w0.z;  acc[r][3] += a[r] * w0.w;
                acc[r][4] += a[r] * w1.x;  acc[r][5] += a[r] * w1.y;
                acc[r][6] += a[r] * w1.z;  acc[r][7] += a[r] * w1.w;
            }
        }
        __syncthreads();
    }
#pragma unroll
    for (int r = 0; r < 4; r++) {
        int grow = row0 + tr * 4 + r;
        if (grow < n) {
            float dv = g_dinv[grow];
            float4 o0 = make_float4(acc[r][0]*dv, acc[r][1]*dv, acc[r][2]*dv, acc[r][3]*dv);
            float4 o1 = make_float4(acc[r][4]*dv, acc[r][5]*dv, acc[r][6]*dv, acc[r][7]*dv);
            *(float4*)&g_h1s[(long long)grow * 128 + tc * 8]     = o0;
            *(float4*)&g_h1s[(long long)grow * 128 + tc * 8 + 4] = o1;
        }
    }
}

// one warp per edge: acc1[dst][0..127] += h1s[src][0..127]
__global__ void scatter1_kernel(const void* ei, long long E) {
    long long warpId = ((long long)blockIdx.x * blockDim.x + threadIdx.x) >> 5;
    int lane = threadIdx.x & 31;
    if (warpId >= E) return;
    int is64 = g_is64;
    long long s = load_idx(ei, warpId, is64);
    long long d = load_idx(ei, E + warpId, is64);
    float4 v = *(const float4*)&g_h1s[s * 128 + lane * 4];
    red_add_v4(&g_acc1[d * 128 + lane * 4], v);
}

// out1 = relu(dinv*acc1 + b1); h2s = (out1 @ W2) * dinv
// 64 rows/block, 128 threads; thread pair splits 16 output cols.
__global__ void layer2_kernel(const float* __restrict__ b1,
                              const float* __restrict__ W2, int n) {
    __shared__ float Sa[64][129];
    __shared__ float W2s[128 * 16];
    const int tid = threadIdx.x;
    const int row0 = blockIdx.x * 64;

    for (int i = tid; i < 2048; i += 128) W2s[i] = W2[i];
    for (int i = tid; i < 64 * 128; i += 128) {
        int r = i >> 7, c = i & 127;
        int grow = row0 + r;
        float v = 0.f;
        if (grow < n)
            v = fmaxf(fmaf(g_dinv[grow], g_acc1[(long long)grow * 128 + c], b1[c]), 0.f);
        Sa[r][c] = v;
    }
    __syncthreads();

    const int r  = tid >> 1;
    const int j0 = (tid & 1) * 8;
    float acc[8];
#pragma unroll
    for (int j = 0; j < 8; j++) acc[j] = 0.f;
#pragma unroll 4
    for (int k = 0; k < 128; k++) {
        float v = Sa[r][k];
#pragma unroll
        for (int j = 0; j < 8; j++) acc[j] += v * W2s[k * 16 + j0 + j];
    }
    int grow = row0 + r;
    if (grow < n) {
        float dv = g_dinv[grow];
        float4 o0 = make_float4(acc[0]*dv, acc[1]*dv, acc[2]*dv, acc[3]*dv);
        float4 o1 = make_float4(acc[4]*dv, acc[5]*dv, acc[6]*dv, acc[7]*dv);
        *(float4*)&g_h2s[(long long)grow * 16 + j0]     = o0;
        *(float4*)&g_h2s[(long long)grow * 16 + j0 + 4] = o1;
    }
}

// 4 lanes per edge: acc2[dst][0..15] += h2s[src][0..15]
__global__ void scatter2_kernel(const void* ei, long long E) {
    long long gt = (long long)blockIdx.x * blockDim.x + threadIdx.x;
    long long e = gt >> 2;
    int sub = (int)(gt & 3);
    if (e >= E) return;
    int is64 = g_is64;
    long long s = load_idx(ei, e, is64);
    long long d = load_idx(ei, E + e, is64);
    float4 v = *(const float4*)&g_h2s[s * 16 + sub * 4];
    red_add_v4(&g_acc2[d * 16 + sub * 4], v);
}

// out = log_softmax(dinv*acc2 + b2)
__global__ void final_kernel(const float* __restrict__ b2, float* __restrict__ out, int n) {
    int i = blockIdx.x * blockDim.x + threadIdx.x;
    if (i >= n) return;
    float dv = g_dinv[i];
    float v[16];
    float mx = -1e30f;
#pragma unroll
    for (int j = 0; j < 16; j++) {
        v[j] = fmaf(dv, g_acc2[(long long)i * 16 + j], b2[j]);
        mx = fmaxf(mx, v[j]);
    }
    float ssum = 0.f;
#pragma unroll
    for (int j = 0; j < 16; j++) ssum += expf(v[j] - mx);
    float lse = mx + logf(ssum);
#pragma unroll
    for (int j = 0; j < 16; j++) out[(long long)i * 16 + j] = v[j] - lse;
}

// ---------------- launch ----------------
extern "C" void kernel_launch(void* const* d_in, const int* in_sizes, int n_in,
                              void* d_out, int out_size) {
    const float* x  = (const float*)d_in[0];
    const void*  ei = d_in[1];
    const float* W1 = (const float*)d_in[2];
    const float* b1 = (const float*)d_in[3];
    const float* W2 = (const float*)d_in[4];
    const float* b2 = (const float*)d_in[5];
    float* out = (float*)d_out;

    long long E = (long long)in_sizes[1] / 2;
    int n = in_sizes[0] / F1;

    detect_kernel<<<1, 1>>>(ei, n);
    zero_kernel<<<512, 256>>>(n);
    deg_kernel<<<(int)((E + 255) / 256), 256>>>(ei, E);
    dinv_kernel<<<(n + 255) / 256, 256>>>(n);
    gemm1_kernel<<<(n + 63) / 64, 256>>>(x, W1, n);
    scatter1_kernel<<<(int)((E + 7) / 8), 256>>>(ei, E);
    layer2_kernel<<<(n + 63) / 64, 128>>>(b1, W2, n);
    scatter2_kernel<<<(int)((E * 4 + 255) / 256), 256>>>(ei, E);
    final_kernel<<<(n + 255) / 256, 256>>>(b2, out, n);
}

// round 3
// speedup vs baseline: 1.0803x; 1.0803x over previous
#include <cuda_runtime.h>
#include <cstdint>
#include <math.h>

#define MAXN 50000
#define MAXE 1000000
#define F1 128
#define F2 16

// ---------------- device scratch ----------------
__device__ __align__(256) float g_dinv[MAXN];
__device__ __align__(256) float g_h1s [MAXN * F1];   // (x@W1) * dinv[row]
__device__ __align__(256) float g_h2s [MAXN * F2];   // per-node layer2 pre-aggregation
__device__ __align__(256) int   g_deg_i[MAXN];
__device__ __align__(256) int   g_cursor[MAXN];
__device__ __align__(256) int   g_row_ptr[MAXN + 1];
__device__ __align__(256) int   g_csr_src[MAXE];
__device__ int g_is64;

// ---------------- helpers ----------------
__device__ __forceinline__ long long load_idx(const void* ei, long long i, int is64) {
    if (is64) return ((const long long*)ei)[i];
    return (long long)((const int*)ei)[i];
}

// ---------------- kernels ----------------

// Detect int32 vs int64 edge_index width.
__global__ void detect_kernel(const void* ei, int n) {
    const long long* p = (const long long*)ei;
    int ok = 1;
    for (int i = 0; i < 8; i++) {
        long long v = p[i];
        if (v < 0 || v >= n) ok = 0;
    }
    g_is64 = ok;
}

__global__ void zero_small_kernel(int n) {
    int i = blockIdx.x * blockDim.x + threadIdx.x;
    if (i < n) { g_deg_i[i] = 0; g_cursor[i] = 0; }
}

__global__ void deg_kernel(const void* ei, long long E) {
    long long i = (long long)blockIdx.x * blockDim.x + threadIdx.x;
    if (i >= E) return;
    int d = (int)load_idx(ei, E + i, g_is64);
    atomicAdd(&g_deg_i[d], 1);
}

// Single-block exclusive scan of degrees -> row_ptr, plus dinv.
__global__ void scan_kernel(int n) {
    __shared__ int wsum[32];
    __shared__ int wexcl[32];
    __shared__ int carry_s;
    const int tid = threadIdx.x, lane = tid & 31, wid = tid >> 5;
    if (tid == 0) carry_s = 0;
    __syncthreads();
    int nchunks = (n + 1023) >> 10;
    for (int c = 0; c < nchunks; c++) {
        int i = (c << 10) + tid;
        int d = (i < n) ? g_deg_i[i] : 0;
        int incl = d;
#pragma unroll
        for (int off = 1; off < 32; off <<= 1) {
            int t = __shfl_up_sync(0xffffffffu, incl, off);
            if (lane >= off) incl += t;
        }
        if (lane == 31) wsum[wid] = incl;
        __syncthreads();
        if (wid == 0) {
            int v = wsum[lane];
            int iv = v;
#pragma unroll
            for (int off = 1; off < 32; off <<= 1) {
                int t = __shfl_up_sync(0xffffffffu, iv, off);
                if (lane >= off) iv += t;
            }
            wexcl[lane] = iv - v;
        }
        __syncthreads();
        int base = carry_s + wexcl[wid];
        if (i < n) {
            g_row_ptr[i] = base + incl - d;
            g_dinv[i] = rsqrtf((float)(d > 0 ? d : 1));
        }
        __syncthreads();
        if (tid == 1023) carry_s = base + incl;   // = carry + chunk total
        __syncthreads();
    }
    if (tid == 0) g_row_ptr[n] = carry_s;
}

__global__ void fill_kernel(const void* ei, long long E) {
    long long i = (long long)blockIdx.x * blockDim.x + threadIdx.x;
    if (i >= E) return;
    int is64 = g_is64;
    int s = (int)load_idx(ei, i, is64);
    int d = (int)load_idx(ei, E + i, is64);
    int p = atomicAdd(&g_cursor[d], 1);
    g_csr_src[g_row_ptr[d] + p] = s;
}

// h1s = (x @ W1) * dinv[row].  BM=64, 256 threads, 4x8 thread tile.
__global__ void gemm1_kernel(const float* __restrict__ x,
                             const float* __restrict__ W1, int n) {
    __shared__ float Xs[64][33];
    __shared__ float Ws[32][128];
    const int tid = threadIdx.x;
    const int tr = tid >> 4;
    const int tc = tid & 15;
    const int row0 = blockIdx.x * 64;

    float acc[4][8];
#pragma unroll
    for (int r = 0; r < 4; r++)
#pragma unroll
        for (int c = 0; c < 8; c++) acc[r][c] = 0.f;

    for (int k0 = 0; k0 < 128; k0 += 32) {
#pragma unroll
        for (int i = tid; i < 512; i += 256) {
            int r = i >> 3, c4 = i & 7;
            int grow = row0 + r;
            float4 v = make_float4(0.f, 0.f, 0.f, 0.f);
            if (grow < n)
                v = *(const float4*)&x[(long long)grow * 128 + k0 + c4 * 4];
            Xs[r][c4 * 4 + 0] = v.x; Xs[r][c4 * 4 + 1] = v.y;
            Xs[r][c4 * 4 + 2] = v.z; Xs[r][c4 * 4 + 3] = v.w;
        }
#pragma unroll
        for (int i = tid; i < 1024; i += 256) {
            int r = i >> 5, c4 = i & 31;
            *(float4*)&Ws[r][c4 * 4] = *(const float4*)&W1[(long long)(k0 + r) * 128 + c4 * 4];
        }
        __syncthreads();
#pragma unroll
        for (int kk = 0; kk < 32; kk++) {
            float a[4];
#pragma unroll
            for (int r = 0; r < 4; r++) a[r] = Xs[tr * 4 + r][kk];
            float4 w0 = *(float4*)&Ws[kk][tc * 8];
            float4 w1 = *(float4*)&Ws[kk][tc * 8 + 4];
#pragma unroll
            for (int r = 0; r < 4; r++) {
                acc[r][0] += a[r] * w0.x;  acc[r][1] += a[r] * w0.y;
                acc[r][2] += a[r] * w0.z;  acc[r][3] += a[r] * w0.w;
                acc[r][4] += a[r] * w1.x;  acc[r][5] += a[r] * w1.y;
                acc[r][6] += a[r] * w1.z;  acc[r][7] += a[r] * w1.w;
            }
        }
        __syncthreads();
    }
#pragma unroll
    for (int r = 0; r < 4; r++) {
        int grow = row0 + tr * 4 + r;
        if (grow < n) {
            float dv = g_dinv[grow];
            float4 o0 = make_float4(acc[r][0]*dv, acc[r][1]*dv, acc[r][2]*dv, acc[r][3]*dv);
            float4 o1 = make_float4(acc[r][4]*dv, acc[r][5]*dv, acc[r][6]*dv, acc[r][7]*dv);
            *(float4*)&g_h1s[(long long)grow * 128 + tc * 8]     = o0;
            *(float4*)&g_h1s[(long long)grow * 128 + tc * 8 + 4] = o1;
        }
    }
}

// Fused: per-node CSR gather-sum of h1s, relu(dinv*agg + b1), @W2, *dinv -> h2s.
// 8 nodes per 128-thread block (W2 amortized in smem).
#define NPB 8
__global__ void node1_kernel(const float* __restrict__ b1,
                             const float* __restrict__ W2, int n) {
    __shared__ float W2s[2048];
    __shared__ float Sa[128];
    __shared__ float Pp[8][17];
    const int tid = threadIdx.x;           // = feature k
    for (int i = tid; i < 2048; i += 128) W2s[i] = W2[i];
    const float bk = b1[tid];

    int node0 = blockIdx.x * NPB;
#pragma unroll 1
    for (int u = 0; u < NPB; u++) {
        int node = node0 + u;
        if (node >= n) break;
        int beg = g_row_ptr[node];
        int end = g_row_ptr[node + 1];
        float a0 = 0.f, a1 = 0.f, a2 = 0.f, a3 = 0.f;
        int e = beg;
        for (; e + 4 <= end; e += 4) {
            int s0 = g_csr_src[e],     s1 = g_csr_src[e + 1];
            int s2 = g_csr_src[e + 2], s3 = g_csr_src[e + 3];
            a0 += g_h1s[(long long)s0 * 128 + tid];
            a1 += g_h1s[(long long)s1 * 128 + tid];
            a2 += g_h1s[(long long)s2 * 128 + tid];
            a3 += g_h1s[(long long)s3 * 128 + tid];
        }
        for (; e < end; e++)
            a0 += g_h1s[(long long)g_csr_src[e] * 128 + tid];
        float agg = (a0 + a1) + (a2 + a3);
        float dv = g_dinv[node];
        __syncthreads();                       // Sa reuse safety
        Sa[tid] = fmaxf(fmaf(dv, agg, bk), 0.f);
        __syncthreads();
        // W2 GEMM: thread (g=tid>>4, j=tid&15) sums k in [g*16, g*16+16)
        int g = tid >> 4, j = tid & 15;
        float p = 0.f;
#pragma unroll
        for (int kk = 0; kk < 16; kk++)
            p += Sa[g * 16 + kk] * W2s[(g * 16 + kk) * 16 + j];
        Pp[g][j] = p;
        __syncthreads();
        if (tid < 16) {
            float s = 0.f;
#pragma unroll
            for (int gg = 0; gg < 8; gg++) s += Pp[gg][tid];
            g_h2s[(long long)node * 16 + tid] = s * dv;
        }
    }
}

// Fused: per-node CSR gather-sum of h2s + bias + log-softmax -> out.
// One warp per node; lanes split 2 edges x 16 features.
__global__ void node2_kernel(const float* __restrict__ b2,
                             float* __restrict__ out, int n) {
    int warpInBlock = threadIdx.x >> 5;
    int lane = threadIdx.x & 31;
    int node = blockIdx.x * (blockDim.x >> 5) + warpInBlock;
    if (node >= n) return;
    int f = lane & 15;
    int eo = lane >> 4;
    int beg = g_row_ptr[node];
    int end = g_row_ptr[node + 1];
    float acc = 0.f;
    for (int e = beg + eo; e < end; e += 2) {
        int s = g_csr_src[e];
        acc += g_h2s[(long long)s * 16 + f];
    }
    acc += __shfl_xor_sync(0xffffffffu, acc, 16);
    float v = fmaf(g_dinv[node], acc, b2[f]);
    float mx = v;
#pragma unroll
    for (int off = 8; off >= 1; off >>= 1)
        mx = fmaxf(mx, __shfl_xor_sync(0xffffffffu, mx, off));
    float ex = expf(v - mx);
#pragma unroll
    for (int off = 8; off >= 1; off >>= 1)
        ex += __shfl_xor_sync(0xffffffffu, ex, off);
    float lse = mx + logf(ex);
    if (lane < 16)
        out[(long long)node * 16 + f] = v - lse;
}

// ---------------- launch ----------------
extern "C" void kernel_launch(void* const* d_in, const int* in_sizes, int n_in,
                              void* d_out, int out_size) {
    const float* x  = (const float*)d_in[0];
    const void*  ei = d_in[1];
    const float* W1 = (const float*)d_in[2];
    const float* b1 = (const float*)d_in[3];
    const float* W2 = (const float*)d_in[4];
    const float* b2 = (const float*)d_in[5];
    float* out = (float*)d_out;

    long long E = (long long)in_sizes[1] / 2;
    int n = in_sizes[0] / F1;

    detect_kernel<<<1, 1>>>(ei, n);
    zero_small_kernel<<<(n + 255) / 256, 256>>>(n);
    deg_kernel<<<(int)((E + 255) / 256), 256>>>(ei, E);
    scan_kernel<<<1, 1024>>>(n);
    fill_kernel<<<(int)((E + 255) / 256), 256>>>(ei, E);
    gemm1_kernel<<<(n + 63) / 64, 256>>>(x, W1, n);
    node1_kernel<<<(n + NPB - 1) / NPB, 128>>>(b1, W2, n);
    node2_kernel<<<(n + 7) / 8, 256>>>(b2, out, n);
}

// round 7
// speedup vs baseline: 1.2727x; 1.1781x over previous
#include <cuda_runtime.h>
#include <cstdint>
#include <math.h>

#define MAXN 50000
#define MAXE 1000000
#define F1 128
#define F2 16

// ---------------- device scratch ----------------
__device__ __align__(256) float g_dinv[MAXN];
__device__ __align__(256) float g_h1s [MAXN * F1];   // (x@W1) * dinv[row]
__device__ __align__(256) float g_h2s [MAXN * F2];   // per-node layer2 pre-aggregation
__device__ __align__(256) int   g_deg_i[MAXN];
__device__ __align__(256) int   g_cursor[MAXN];
__device__ __align__(256) int   g_row_ptr[MAXN + 1];
__device__ __align__(256) int   g_csr_src[MAXE];
__device__ __align__(256) int   g_bsum[64];
__device__ int g_is64;

// ---------------- helpers ----------------
__device__ __forceinline__ long long load_idx(const void* ei, long long i, int is64) {
    if (is64) return ((const long long*)ei)[i];
    return (long long)((const int*)ei)[i];
}

// ---------------- kernels ----------------

// Zero counters + (block 0, thread 0) detect int32 vs int64 edge_index width.
__global__ void zero_detect_kernel(const void* ei, int n) {
    int i = blockIdx.x * blockDim.x + threadIdx.x;
    if (i < n) { g_deg_i[i] = 0; g_cursor[i] = 0; }
    if (blockIdx.x == 0 && threadIdx.x == 0) {
        const long long* p = (const long long*)ei;
        int ok = 1;
        for (int k = 0; k < 8; k++) {
            long long v = p[k];
            if (v < 0 || v >= n) ok = 0;
        }
        g_is64 = ok;
    }
}

__global__ void deg_kernel(const void* ei, long long E) {
    long long i = (long long)blockIdx.x * blockDim.x + threadIdx.x;
    if (i >= E) return;
    int d = (int)load_idx(ei, E + i, g_is64);
    atomicAdd(&g_deg_i[d], 1);
}

// Phase 1: per-block local scan. 1024 threads/block.
// Writes local-exclusive prefix into g_row_ptr[i] and block total into g_bsum[bid].
__global__ void scan1_kernel(int n) {
    __shared__ int wsum[32];
    __shared__ int wexcl[32];
    const int tid = threadIdx.x, lane = tid & 31, wid = tid >> 5;
    int i = blockIdx.x * 1024 + tid;
    int d = (i < n) ? g_deg_i[i] : 0;
    int incl = d;
#pragma unroll
    for (int off = 1; off < 32; off <<= 1) {
        int t = __shfl_up_sync(0xffffffffu, incl, off);
        if (lane >= off) incl += t;
    }
    if (lane == 31) wsum[wid] = incl;
    __syncthreads();
    if (wid == 0) {
        int v = wsum[lane];
        int iv = v;
#pragma unroll
        for (int off = 1; off < 32; off <<= 1) {
            int t = __shfl_up_sync(0xffffffffu, iv, off);
            if (lane >= off) iv += t;
        }
        wexcl[lane] = iv - v;
    }
    __syncthreads();
    if (i < n) g_row_ptr[i] = wexcl[wid] + incl - d;
    if (tid == 1023) g_bsum[blockIdx.x] = wexcl[31] + incl;
}

// Phase 2: add per-block offsets; compute dinv; write row_ptr[n].
__global__ void scan2_kernel(int n, int nblocks) {
    __shared__ int offset_s;
    const int tid = threadIdx.x;
    if (tid < 32) {
        int acc = 0;
        for (int j = tid; j < blockIdx.x; j += 32) acc += g_bsum[j];
#pragma unroll
        for (int off = 16; off >= 1; off >>= 1)
            acc += __shfl_xor_sync(0xffffffffu, acc, off);
        if (tid == 0) offset_s = acc;
    }
    __syncthreads();
    int i = blockIdx.x * 1024 + tid;
    if (i < n) {
        g_row_ptr[i] += offset_s;
        int d = g_deg_i[i];
        g_dinv[i] = rsqrtf((float)(d > 0 ? d : 1));
    }
    if ((int)blockIdx.x == nblocks - 1 && tid == 0)
        g_row_ptr[n] = offset_s + g_bsum[blockIdx.x];
}

__global__ void fill_kernel(const void* ei, long long E) {
    long long i = (long long)blockIdx.x * blockDim.x + threadIdx.x;
    if (i >= E) return;
    int is64 = g_is64;
    int s = (int)load_idx(ei, i, is64);
    int d = (int)load_idx(ei, E + i, is64);
    int p = atomicAdd(&g_cursor[d], 1);
    g_csr_src[g_row_ptr[d] + p] = s;
}

// h1s = (x @ W1) * dinv[row].  BM=64, 256 threads, 4x8 thread tile.
__global__ void gemm1_kernel(const float* __restrict__ x,
                             const float* __restrict__ W1, int n) {
    __shared__ float Xs[64][33];
    __shared__ float Ws[32][128];
    const int tid = threadIdx.x;
    const int tr = tid >> 4;
    const int tc = tid & 15;
    const int row0 = blockIdx.x * 64;

    float acc[4][8];
#pragma unroll
    for (int r = 0; r < 4; r++)
#pragma unroll
        for (int c = 0; c < 8; c++) acc[r][c] = 0.f;

    for (int k0 = 0; k0 < 128; k0 += 32) {
#pragma unroll
        for (int i = tid; i < 512; i += 256) {
            int r = i >> 3, c4 = i & 7;
            int grow = row0 + r;
            float4 v = make_float4(0.f, 0.f, 0.f, 0.f);
            if (grow < n)
                v = *(const float4*)&x[(long long)grow * 128 + k0 + c4 * 4];
            Xs[r][c4 * 4 + 0] = v.x; Xs[r][c4 * 4 + 1] = v.y;
            Xs[r][c4 * 4 + 2] = v.z; Xs[r][c4 * 4 + 3] = v.w;
        }
#pragma unroll
        for (int i = tid; i < 1024; i += 256) {
            int r = i >> 5, c4 = i & 31;
            *(float4*)&Ws[r][c4 * 4] = *(const float4*)&W1[(long long)(k0 + r) * 128 + c4 * 4];
        }
        __syncthreads();
#pragma unroll
        for (int kk = 0; kk < 32; kk++) {
            float a[4];
#pragma unroll
            for (int r = 0; r < 4; r++) a[r] = Xs[tr * 4 + r][kk];
            float4 w0 = *(float4*)&Ws[kk][tc * 8];
            float4 w1 = *(float4*)&Ws[kk][tc * 8 + 4];
#pragma unroll
            for (int r = 0; r < 4; r++) {
                acc[r][0] += a[r] * w0.x;  acc[r][1] += a[r] * w0.y;
                acc[r][2] += a[r] * w0.z;  acc[r][3] += a[r] * w0.w;
                acc[r][4] += a[r] * w1.x;  acc[r][5] += a[r] * w1.y;
                acc[r][6] += a[r] * w1.z;  acc[r][7] += a[r] * w1.w;
            }
        }
        __syncthreads();
    }
#pragma unroll
    for (int r = 0; r < 4; r++) {
        int grow = row0 + tr * 4 + r;
        if (grow < n) {
            float dv = g_dinv[grow];
            float4 o0 = make_float4(acc[r][0]*dv, acc[r][1]*dv, acc[r][2]*dv, acc[r][3]*dv);
            float4 o1 = make_float4(acc[r][4]*dv, acc[r][5]*dv, acc[r][6]*dv, acc[r][7]*dv);
            *(float4*)&g_h1s[(long long)grow * 128 + tc * 8]     = o0;
            *(float4*)&g_h1s[(long long)grow * 128 + tc * 8 + 4] = o1;
        }
    }
}

// Fused: per-node CSR gather-sum of h1s, relu(dinv*agg + b1), @W2, *dinv -> h2s.
// 8 nodes per 128-thread block (W2 amortized in smem).
#define NPB 8
__global__ void node1_kernel(const float* __restrict__ b1,
                             const float* __restrict__ W2, int n) {
    __shared__ float W2s[2048];
    __shared__ float Sa[128];
    __shared__ float Pp[8][17];
    const int tid = threadIdx.x;           // = feature k
    for (int i = tid; i < 2048; i += 128) W2s[i] = W2[i];
    const float bk = b1[tid];

    int node0 = blockIdx.x * NPB;
#pragma unroll 1
    for (int u = 0; u < NPB; u++) {
        int node = node0 + u;
        if (node >= n) break;
        int beg = g_row_ptr[node];
        int end = g_row_ptr[node + 1];
        float a0 = 0.f, a1 = 0.f, a2 = 0.f, a3 = 0.f;
        int e = beg;
        for (; e + 4 <= end; e += 4) {
            int s0 = g_csr_src[e],     s1 = g_csr_src[e + 1];
            int s2 = g_csr_src[e + 2], s3 = g_csr_src[e + 3];
            a0 += g_h1s[(long long)s0 * 128 + tid];
            a1 += g_h1s[(long long)s1 * 128 + tid];
            a2 += g_h1s[(long long)s2 * 128 + tid];
            a3 += g_h1s[(long long)s3 * 128 + tid];
        }
        for (; e < end; e++)
            a0 += g_h1s[(long long)g_csr_src[e] * 128 + tid];
        float agg = (a0 + a1) + (a2 + a3);
        float dv = g_dinv[node];
        __syncthreads();                       // Sa reuse safety
        Sa[tid] = fmaxf(fmaf(dv, agg, bk), 0.f);
        __syncthreads();
        // W2 GEMM: thread (g=tid>>4, j=tid&15) sums k in [g*16, g*16+16)
        int g = tid >> 4, j = tid & 15;
        float p = 0.f;
#pragma unroll
        for (int kk = 0; kk < 16; kk++)
            p += Sa[g * 16 + kk] * W2s[(g * 16 + kk) * 16 + j];
        Pp[g][j] = p;
        __syncthreads();
        if (tid < 16) {
            float s = 0.f;
#pragma unroll
            for (int gg = 0; gg < 8; gg++) s += Pp[gg][tid];
            g_h2s[(long long)node * 16 + tid] = s * dv;
        }
    }
}

// Fused: per-node CSR gather-sum of h2s + bias + log-softmax -> out.
// One warp per node; lanes split 2 edges x 16 features.
__global__ void node2_kernel(const float* __restrict__ b2,
                             float* __restrict__ out, int n) {
    int warpInBlock = threadIdx.x >> 5;
    int lane = threadIdx.x & 31;
    int node = blockIdx.x * (blockDim.x >> 5) + warpInBlock;
    if (node >= n) return;
    int f = lane & 15;
    int eo = lane >> 4;
    int beg = g_row_ptr[node];
    int end = g_row_ptr[node + 1];
    float acc = 0.f;
    for (int e = beg + eo; e < end; e += 2) {
        int s = g_csr_src[e];
        acc += g_h2s[(long long)s * 16 + f];
    }
    acc += __shfl_xor_sync(0xffffffffu, acc, 16);
    float v = fmaf(g_dinv[node], acc, b2[f]);
    float mx = v;
#pragma unroll
    for (int off = 8; off >= 1; off >>= 1)
        mx = fmaxf(mx, __shfl_xor_sync(0xffffffffu, mx, off));
    float ex = expf(v - mx);
#pragma unroll
    for (int off = 8; off >= 1; off >>= 1)
        ex += __shfl_xor_sync(0xffffffffu, ex, off);
    float lse = mx + logf(ex);
    if (lane < 16)
        out[(long long)node * 16 + f] = v - lse;
}

// ---------------- launch ----------------
extern "C" void kernel_launch(void* const* d_in, const int* in_sizes, int n_in,
                              void* d_out, int out_size) {
    const float* x  = (const float*)d_in[0];
    const void*  ei = d_in[1];
    const float* W1 = (const float*)d_in[2];
    const float* b1 = (const float*)d_in[3];
    const float* W2 = (const float*)d_in[4];
    const float* b2 = (const float*)d_in[5];
    float* out = (float*)d_out;

    long long E = (long long)in_sizes[1] / 2;
    int n = in_sizes[0] / F1;
    int nScanBlocks = (n + 1023) / 1024;

    zero_detect_kernel<<<(n + 255) / 256, 256>>>(ei, n);
    deg_kernel<<<(int)((E + 255) / 256), 256>>>(ei, E);
    scan1_kernel<<<nScanBlocks, 1024>>>(n);
    scan2_kernel<<<nScanBlocks, 1024>>>(n, nScanBlocks);
    fill_kernel<<<(int)((E + 255) / 256), 256>>>(ei, E);
    gemm1_kernel<<<(n + 63) / 64, 256>>>(x, W1, n);
    node1_kernel<<<(n + NPB - 1) / NPB, 128>>>(b1, W2, n);
    node2_kernel<<<(n + 7) / 8, 256>>>(b2, out, n);
}

// round 8
// speedup vs baseline: 1.6434x; 1.2913x over previous
#include <cuda_runtime.h>
#include <cstdint>
#include <math.h>

#define MAXN 50000
#define MAXE 1000000
#define F1 128
#define F2 16

typedef unsigned long long ull;

// ---------------- device scratch ----------------
__device__ __align__(256) float g_dinv[MAXN];
__device__ __align__(256) float g_h1s [MAXN * F1];   // (x@W1) * dinv[row]
__device__ __align__(256) float g_h2s [MAXN * F2];   // per-node layer2 pre-aggregation
__device__ __align__(256) int   g_deg_i[MAXN];
__device__ __align__(256) int   g_cursor[MAXN];
__device__ __align__(256) int   g_row_ptr[MAXN + 1];
__device__ __align__(256) int   g_csr_src[MAXE];
__device__ __align__(256) int   g_bsum[64];
__device__ int g_is64;

// ---------------- helpers ----------------
__device__ __forceinline__ long long load_idx(const void* ei, long long i, int is64) {
    if (is64) return ((const long long*)ei)[i];
    return (long long)((const int*)ei)[i];
}

__device__ __forceinline__ void fma2(ull& d, ull a, ull b) {
    asm("fma.rn.f32x2 %0, %1, %2, %3;" : "=l"(d) : "l"(a), "l"(b), "l"(d));
}
__device__ __forceinline__ float unpack_sum(ull v) {
    float lo, hi;
    asm("mov.b64 {%0,%1}, %2;" : "=f"(lo), "=f"(hi) : "l"(v));
    return lo + hi;
}

// ---------------- kernels ----------------

__global__ void zero_detect_kernel(const void* ei, int n) {
    int i = blockIdx.x * blockDim.x + threadIdx.x;
    if (i < n) { g_deg_i[i] = 0; g_cursor[i] = 0; }
    if (blockIdx.x == 0 && threadIdx.x == 0) {
        const long long* p = (const long long*)ei;
        int ok = 1;
        for (int k = 0; k < 8; k++) {
            long long v = p[k];
            if (v < 0 || v >= n) ok = 0;
        }
        g_is64 = ok;
    }
}

__global__ void deg_kernel(const void* ei, long long E) {
    long long i = (long long)blockIdx.x * blockDim.x + threadIdx.x;
    if (i >= E) return;
    int d = (int)load_idx(ei, E + i, g_is64);
    atomicAdd(&g_deg_i[d], 1);
}

__global__ void scan1_kernel(int n) {
    __shared__ int wsum[32];
    __shared__ int wexcl[32];
    const int tid = threadIdx.x, lane = tid & 31, wid = tid >> 5;
    int i = blockIdx.x * 1024 + tid;
    int d = (i < n) ? g_deg_i[i] : 0;
    int incl = d;
#pragma unroll
    for (int off = 1; off < 32; off <<= 1) {
        int t = __shfl_up_sync(0xffffffffu, incl, off);
        if (lane >= off) incl += t;
    }
    if (lane == 31) wsum[wid] = incl;
    __syncthreads();
    if (wid == 0) {
        int v = wsum[lane];
        int iv = v;
#pragma unroll
        for (int off = 1; off < 32; off <<= 1) {
            int t = __shfl_up_sync(0xffffffffu, iv, off);
            if (lane >= off) iv += t;
        }
        wexcl[lane] = iv - v;
    }
    __syncthreads();
    if (i < n) g_row_ptr[i] = wexcl[wid] + incl - d;
    if (tid == 1023) g_bsum[blockIdx.x] = wexcl[31] + incl;
}

__global__ void scan2_kernel(int n, int nblocks) {
    __shared__ int offset_s;
    const int tid = threadIdx.x;
    if (tid < 32) {
        int acc = 0;
        for (int j = tid; j < blockIdx.x; j += 32) acc += g_bsum[j];
#pragma unroll
        for (int off = 16; off >= 1; off >>= 1)
            acc += __shfl_xor_sync(0xffffffffu, acc, off);
        if (tid == 0) offset_s = acc;
    }
    __syncthreads();
    int i = blockIdx.x * 1024 + tid;
    if (i < n) {
        g_row_ptr[i] += offset_s;
        int d = g_deg_i[i];
        g_dinv[i] = rsqrtf((float)(d > 0 ? d : 1));
    }
    if ((int)blockIdx.x == nblocks - 1 && tid == 0)
        g_row_ptr[n] = offset_s + g_bsum[blockIdx.x];
}

__global__ void fill_kernel(const void* ei, long long E) {
    long long i = (long long)blockIdx.x * blockDim.x + threadIdx.x;
    if (i >= E) return;
    int is64 = g_is64;
    int s = (int)load_idx(ei, i, is64);
    int d = (int)load_idx(ei, E + i, is64);
    int p = atomicAdd(&g_cursor[d], 1);
    g_csr_src[g_row_ptr[d] + p] = s;
}

// h1s = (x @ W1) * dinv[row]. BM=64, 256 threads.
// Thread (tr=tid>>4, tc=tid&15): rows tr*4..+4, cols {tc+16j, j=0..7}.
// f32x2 packed FMAs accumulating partial sums over k-pairs.
__global__ void gemm1_kernel(const float* __restrict__ x,
                             const float* __restrict__ W1, int n) {
    __shared__ float Xs[64][36];            // k-pairs along row; 8B-aligned pairs
    __shared__ float Wkp[16 * 256];         // Wkp[kp][c][2] = W1[k0+2kp+t][c]
    const int tid = threadIdx.x;
    const int tr = tid >> 4;
    const int tc = tid & 15;
    const int row0 = blockIdx.x * 64;

    ull acc2[4][8];
#pragma unroll
    for (int r = 0; r < 4; r++)
#pragma unroll
        for (int j = 0; j < 8; j++) acc2[r][j] = 0ull;

    for (int k0 = 0; k0 < 128; k0 += 32) {
#pragma unroll
        for (int i = tid; i < 512; i += 256) {
            int r = i >> 3, c4 = i & 7;
            int grow = row0 + r;
            float4 v = make_float4(0.f, 0.f, 0.f, 0.f);
            if (grow < n)
                v = *(const float4*)&x[(long long)grow * 128 + k0 + c4 * 4];
            *(float4*)&Xs[r][c4 * 4] = v;
        }
#pragma unroll
        for (int i = tid; i < 1024; i += 256) {
            int kr = i >> 5, c4 = i & 31;
            float4 v = *(const float4*)&W1[(long long)(k0 + kr) * 128 + c4 * 4];
            int base = (kr >> 1) * 256 + (kr & 1);
            Wkp[base + (c4 * 4 + 0) * 2] = v.x;
            Wkp[base + (c4 * 4 + 1) * 2] = v.y;
            Wkp[base + (c4 * 4 + 2) * 2] = v.z;
            Wkp[base + (c4 * 4 + 3) * 2] = v.w;
        }
        __syncthreads();
#pragma unroll
        for (int kp = 0; kp < 16; kp++) {
            ull a01[4];
#pragma unroll
            for (int r = 0; r < 4; r++)
                a01[r] = *(const ull*)&Xs[tr * 4 + r][2 * kp];
#pragma unroll
            for (int j = 0; j < 8; j++) {
                ull w = *(const ull*)&Wkp[kp * 256 + (tc + 16 * j) * 2];
#pragma unroll
                for (int r = 0; r < 4; r++) fma2(acc2[r][j], a01[r], w);
            }
        }
        __syncthreads();
    }
#pragma unroll
    for (int r = 0; r < 4; r++) {
        int grow = row0 + tr * 4 + r;
        if (grow < n) {
            float dv = g_dinv[grow];
#pragma unroll
            for (int j = 0; j < 8; j++)
                g_h1s[(long long)grow * 128 + tc + 16 * j] = unpack_sum(acc2[r][j]) * dv;
        }
    }
}

// Fused: warp-per-node CSR gather (float4/lane) + relu + W2 (f32x2) + dinv -> h2s.
// 128 threads = 4 warps = 4 concurrent nodes; 8 nodes per block in 2 chunks.
#define NPB 8
__global__ void node1_kernel(const float* __restrict__ b1,
                             const float* __restrict__ W2, int n) {
    __shared__ float W2p[64 * 32];          // W2p[k>>1][j][k&1]
    __shared__ float Sa[4][128];            // warp-private rows
    const int tid = threadIdx.x;
    const int wid = tid >> 5;
    const int lane = tid & 31;
    const unsigned FULL = 0xffffffffu;

    for (int i = tid; i < 2048; i += 128) {
        int k = i >> 4, j = i & 15;
        W2p[(k >> 1) * 32 + j * 2 + (k & 1)] = W2[i];
    }
    float4 b4 = ((const float4*)b1)[lane];
    __syncthreads();

    const int g2 = lane >> 4;               // k-half for W2 phase
    const int j  = lane & 15;               // output class
    int node0 = blockIdx.x * NPB;

#pragma unroll
    for (int ch = 0; ch < 2; ch++) {
        int node = node0 + ch * 4 + wid;
        if (node < n) {
            int beg = g_row_ptr[node];
            int end = g_row_ptr[node + 1];
            float4 acc0 = make_float4(0.f, 0.f, 0.f, 0.f);
            float4 acc1 = make_float4(0.f, 0.f, 0.f, 0.f);
            for (int base = beg; base < end; base += 32) {
                int cnt = end - base; if (cnt > 32) cnt = 32;
                int idx = base + lane;
                int mysrc = (idx < end) ? g_csr_src[idx] : 0;
                int t = 0;
                for (; t + 4 <= cnt; t += 4) {
                    int s0 = __shfl_sync(FULL, mysrc, t);
                    int s1 = __shfl_sync(FULL, mysrc, t + 1);
                    int s2 = __shfl_sync(FULL, mysrc, t + 2);
                    int s3 = __shfl_sync(FULL, mysrc, t + 3);
                    float4 v0 = *(const float4*)&g_h1s[(long long)s0 * 128 + lane * 4];
                    float4 v1 = *(const float4*)&g_h1s[(long long)s1 * 128 + lane * 4];
                    float4 v2 = *(const float4*)&g_h1s[(long long)s2 * 128 + lane * 4];
                    float4 v3 = *(const float4*)&g_h1s[(long long)s3 * 128 + lane * 4];
                    acc0.x += v0.x; acc0.y += v0.y; acc0.z += v0.z; acc0.w += v0.w;
                    acc1.x += v1.x; acc1.y += v1.y; acc1.z += v1.z; acc1.w += v1.w;
                    acc0.x += v2.x; acc0.y += v2.y; acc0.z += v2.z; acc0.w += v2.w;
                    acc1.x += v3.x; acc1.y += v3.y; acc1.z += v3.z; acc1.w += v3.w;
                }
                for (; t < cnt; t++) {
                    int s = __shfl_sync(FULL, mysrc, t);
                    float4 v = *(const float4*)&g_h1s[(long long)s * 128 + lane * 4];
                    acc0.x += v.x; acc0.y += v.y; acc0.z += v.z; acc0.w += v.w;
                }
            }
            float dv = g_dinv[node];
            float4 sv;
            sv.x = fmaxf(fmaf(dv, acc0.x + acc1.x, b4.x), 0.f);
            sv.y = fmaxf(fmaf(dv, acc0.y + acc1.y, b4.y), 0.f);
            sv.z = fmaxf(fmaf(dv, acc0.z + acc1.z, b4.z), 0.f);
            sv.w = fmaxf(fmaf(dv, acc0.w + acc1.w, b4.w), 0.f);
            *(float4*)&Sa[wid][lane * 4] = sv;
            __syncwarp();
            // W2: lane (g2, j) covers k in [g2*64, g2*64+64), pairs via f32x2
            ull acc2 = 0ull;
#pragma unroll
            for (int kp = 0; kp < 32; kp++) {
                int k = g2 * 64 + 2 * kp;
                ull a = *(const ull*)&Sa[wid][k];
                ull w = *(const ull*)&W2p[(k >> 1) * 32 + j * 2];
                fma2(acc2, a, w);
            }
            float part = unpack_sum(acc2);
            part += __shfl_xor_sync(FULL, part, 16);
            if (lane < 16)
                g_h2s[(long long)node * 16 + j] = part * dv;
            __syncwarp();
        }
    }
}

// Fused: per-node CSR gather-sum of h2s + bias + log-softmax -> out.
__global__ void node2_kernel(const float* __restrict__ b2,
                             float* __restrict__ out, int n) {
    int warpInBlock = threadIdx.x >> 5;
    int lane = threadIdx.x & 31;
    int node = blockIdx.x * (blockDim.x >> 5) + warpInBlock;
    if (node >= n) return;
    int f = lane & 15;
    int eo = lane >> 4;
    int beg = g_row_ptr[node];
    int end = g_row_ptr[node + 1];
    float acc = 0.f;
    for (int e = beg + eo; e < end; e += 2) {
        int s = g_csr_src[e];
        acc += g_h2s[(long long)s * 16 + f];
    }
    acc += __shfl_xor_sync(0xffffffffu, acc, 16);
    float v = fmaf(g_dinv[node], acc, b2[f]);
    float mx = v;
#pragma unroll
    for (int off = 8; off >= 1; off >>= 1)
        mx = fmaxf(mx, __shfl_xor_sync(0xffffffffu, mx, off));
    float ex = expf(v - mx);
#pragma unroll
    for (int off = 8; off >= 1; off >>= 1)
        ex += __shfl_xor_sync(0xffffffffu, ex, off);
    float lse = mx + logf(ex);
    if (lane < 16)
        out[(long long)node * 16 + f] = v - lse;
}

// ---------------- launch ----------------
extern "C" void kernel_launch(void* const* d_in, const int* in_sizes, int n_in,
                              void* d_out, int out_size) {
    const float* x  = (const float*)d_in[0];
    const void*  ei = d_in[1];
    const float* W1 = (const float*)d_in[2];
    const float* b1 = (const float*)d_in[3];
    const float* W2 = (const float*)d_in[4];
    const float* b2 = (const float*)d_in[5];
    float* out = (float*)d_out;

    long long E = (long long)in_sizes[1] / 2;
    int n = in_sizes[0] / F1;
    int nScanBlocks = (n + 1023) / 1024;

    zero_detect_kernel<<<(n + 255) / 256, 256>>>(ei, n);
    deg_kernel<<<(int)((E + 255) / 256), 256>>>(ei, E);
    scan1_kernel<<<nScanBlocks, 1024>>>(n);
    scan2_kernel<<<nScanBlocks, 1024>>>(n, nScanBlocks);
    fill_kernel<<<(int)((E + 255) / 256), 256>>>(ei, E);
    gemm1_kernel<<<(n + 63) / 64, 256>>>(x, W1, n);
    node1_kernel<<<(n + NPB - 1) / NPB, 128>>>(b1, W2, n);
    node2_kernel<<<(n + 7) / 8, 256>>>(b2, out, n);
}

// round 9
// speedup vs baseline: 1.7304x; 1.0529x over previous
#include <cuda_runtime.h>
#include <cuda_fp16.h>
#include <cstdint>
#include <math.h>

#define MAXN 50000
#define MAXE 1000000
#define F1 128
#define F2 16

typedef unsigned long long ull;

// ---------------- device scratch ----------------
__device__ __align__(256) float  g_dinv[MAXN];
__device__ __align__(256) __half g_h1s [MAXN * F1];  // fp16: (x@W1) * dinv[row]
__device__ __align__(256) float  g_h2s [MAXN * F2];
__device__ __align__(256) int    g_deg_i[MAXN];
__device__ __align__(256) int    g_cursor[MAXN];
__device__ __align__(256) int    g_row_ptr[MAXN + 1];
__device__ __align__(256) int    g_csr_src[MAXE];
__device__ __align__(256) int    g_bsum[64];
__device__ int g_is64;

// ---------------- helpers ----------------
__device__ __forceinline__ long long load_idx(const void* ei, long long i, int is64) {
    if (is64) return ((const long long*)ei)[i];
    return (long long)((const int*)ei)[i];
}

__device__ __forceinline__ void fma2(ull& d, ull a, ull b) {
    asm("fma.rn.f32x2 %0, %1, %2, %3;" : "=l"(d) : "l"(a), "l"(b), "l"(d));
}
__device__ __forceinline__ float unpack_sum(ull v) {
    float lo, hi;
    asm("mov.b64 {%0,%1}, %2;" : "=f"(lo), "=f"(hi) : "l"(v));
    return lo + hi;
}

// ---------------- kernels ----------------

__global__ void zero_detect_kernel(const void* ei, int n) {
    int i = blockIdx.x * blockDim.x + threadIdx.x;
    if (i < n) { g_deg_i[i] = 0; g_cursor[i] = 0; }
    if (blockIdx.x == 0 && threadIdx.x == 0) {
        const long long* p = (const long long*)ei;
        int ok = 1;
        for (int k = 0; k < 8; k++) {
            long long v = p[k];
            if (v < 0 || v >= n) ok = 0;
        }
        g_is64 = ok;
    }
}

__global__ void deg_kernel(const void* ei, long long E) {
    long long i = (long long)blockIdx.x * blockDim.x + threadIdx.x;
    if (i >= E) return;
    int d = (int)load_idx(ei, E + i, g_is64);
    atomicAdd(&g_deg_i[d], 1);
}

__global__ void scan1_kernel(int n) {
    __shared__ int wsum[32];
    __shared__ int wexcl[32];
    const int tid = threadIdx.x, lane = tid & 31, wid = tid >> 5;
    int i = blockIdx.x * 1024 + tid;
    int d = (i < n) ? g_deg_i[i] : 0;
    int incl = d;
#pragma unroll
    for (int off = 1; off < 32; off <<= 1) {
        int t = __shfl_up_sync(0xffffffffu, incl, off);
        if (lane >= off) incl += t;
    }
    if (lane == 31) wsum[wid] = incl;
    __syncthreads();
    if (wid == 0) {
        int v = wsum[lane];
        int iv = v;
#pragma unroll
        for (int off = 1; off < 32; off <<= 1) {
            int t = __shfl_up_sync(0xffffffffu, iv, off);
            if (lane >= off) iv += t;
        }
        wexcl[lane] = iv - v;
    }
    __syncthreads();
    if (i < n) g_row_ptr[i] = wexcl[wid] + incl - d;
    if (tid == 1023) g_bsum[blockIdx.x] = wexcl[31] + incl;
}

__global__ void scan2_kernel(int n, int nblocks) {
    __shared__ int offset_s;
    const int tid = threadIdx.x;
    if (tid < 32) {
        int acc = 0;
        for (int j = tid; j < blockIdx.x; j += 32) acc += g_bsum[j];
#pragma unroll
        for (int off = 16; off >= 1; off >>= 1)
            acc += __shfl_xor_sync(0xffffffffu, acc, off);
        if (tid == 0) offset_s = acc;
    }
    __syncthreads();
    int i = blockIdx.x * 1024 + tid;
    if (i < n) {
        g_row_ptr[i] += offset_s;
        int d = g_deg_i[i];
        g_dinv[i] = rsqrtf((float)(d > 0 ? d : 1));
    }
    if ((int)blockIdx.x == nblocks - 1 && tid == 0)
        g_row_ptr[n] = offset_s + g_bsum[blockIdx.x];
}

__global__ void fill_kernel(const void* ei, long long E) {
    long long i = (long long)blockIdx.x * blockDim.x + threadIdx.x;
    if (i >= E) return;
    int is64 = g_is64;
    int s = (int)load_idx(ei, i, is64);
    int d = (int)load_idx(ei, E + i, is64);
    int p = atomicAdd(&g_cursor[d], 1);
    g_csr_src[g_row_ptr[d] + p] = s;
}

// h1s = fp16((x @ W1) * dinv[row]). BM=64, 256 threads, f32x2 FMAs.
// Thread (tr, tc): rows tr*4..+4, cols {tc+16j}. Epilogue packs col pairs
// (tc+16j, tc+16j+... ) as scalar half stores (small traffic).
__global__ void gemm1_kernel(const float* __restrict__ x,
                             const float* __restrict__ W1, int n) {
    __shared__ float Xs[64][36];
    __shared__ float Wkp[16 * 256];
    const int tid = threadIdx.x;
    const int tr = tid >> 4;
    const int tc = tid & 15;
    const int row0 = blockIdx.x * 64;

    ull acc2[4][8];
#pragma unroll
    for (int r = 0; r < 4; r++)
#pragma unroll
        for (int j = 0; j < 8; j++) acc2[r][j] = 0ull;

    for (int k0 = 0; k0 < 128; k0 += 32) {
#pragma unroll
        for (int i = tid; i < 512; i += 256) {
            int r = i >> 3, c4 = i & 7;
            int grow = row0 + r;
            float4 v = make_float4(0.f, 0.f, 0.f, 0.f);
            if (grow < n)
                v = *(const float4*)&x[(long long)grow * 128 + k0 + c4 * 4];
            *(float4*)&Xs[r][c4 * 4] = v;
        }
#pragma unroll
        for (int i = tid; i < 1024; i += 256) {
            int kr = i >> 5, c4 = i & 31;
            float4 v = *(const float4*)&W1[(long long)(k0 + kr) * 128 + c4 * 4];
            int base = (kr >> 1) * 256 + (kr & 1);
            Wkp[base + (c4 * 4 + 0) * 2] = v.x;
            Wkp[base + (c4 * 4 + 1) * 2] = v.y;
            Wkp[base + (c4 * 4 + 2) * 2] = v.z;
            Wkp[base + (c4 * 4 + 3) * 2] = v.w;
        }
        __syncthreads();
#pragma unroll
        for (int kp = 0; kp < 16; kp++) {
            ull a01[4];
#pragma unroll
            for (int r = 0; r < 4; r++)
                a01[r] = *(const ull*)&Xs[tr * 4 + r][2 * kp];
#pragma unroll
            for (int j = 0; j < 8; j++) {
                ull w = *(const ull*)&Wkp[kp * 256 + (tc + 16 * j) * 2];
#pragma unroll
                for (int r = 0; r < 4; r++) fma2(acc2[r][j], a01[r], w);
            }
        }
        __syncthreads();
    }
#pragma unroll
    for (int r = 0; r < 4; r++) {
        int grow = row0 + tr * 4 + r;
        if (grow < n) {
            float dv = g_dinv[grow];
#pragma unroll
            for (int j = 0; j < 8; j++)
                g_h1s[(long long)grow * 128 + tc + 16 * j] =
                    __float2half(unpack_sum(acc2[r][j]) * dv);
        }
    }
}

// Fused: warp-per-node CSR gather of fp16 h1s (uint2/lane = 4 halves),
// fp32 accumulate, relu+b1, @W2 (f32x2), *dinv -> h2s (fp32).
#define NPB 8
__global__ void node1_kernel(const float* __restrict__ b1,
                             const float* __restrict__ W2, int n) {
    __shared__ float W2p[64 * 32];          // W2p[k>>1][j][k&1]
    __shared__ float Sa[4][128];            // warp-private rows
    const int tid = threadIdx.x;
    const int wid = tid >> 5;
    const int lane = tid & 31;
    const unsigned FULL = 0xffffffffu;

    for (int i = tid; i < 2048; i += 128) {
        int k = i >> 4, j = i & 15;
        W2p[(k >> 1) * 32 + j * 2 + (k & 1)] = W2[i];
    }
    float4 b4 = ((const float4*)b1)[lane];
    __syncthreads();

    const int g2 = lane >> 4;
    const int j  = lane & 15;
    const __half* h1 = g_h1s;
    int node0 = blockIdx.x * NPB;

#pragma unroll
    for (int ch = 0; ch < 2; ch++) {
        int node = node0 + ch * 4 + wid;
        if (node < n) {
            int beg = g_row_ptr[node];
            int end = g_row_ptr[node + 1];
            // lane covers features [lane*4, lane*4+4): 2 float2 accumulators x2 for ILP
            float2 accA0 = make_float2(0.f, 0.f), accA1 = make_float2(0.f, 0.f);
            float2 accB0 = make_float2(0.f, 0.f), accB1 = make_float2(0.f, 0.f);
            for (int base = beg; base < end; base += 32) {
                int cnt = end - base; if (cnt > 32) cnt = 32;
                int idx = base + lane;
                int mysrc = (idx < end) ? g_csr_src[idx] : 0;
                int t = 0;
                for (; t + 4 <= cnt; t += 4) {
                    int s0 = __shfl_sync(FULL, mysrc, t);
                    int s1 = __shfl_sync(FULL, mysrc, t + 1);
                    int s2 = __shfl_sync(FULL, mysrc, t + 2);
                    int s3 = __shfl_sync(FULL, mysrc, t + 3);
                    uint2 v0 = *(const uint2*)&h1[(long long)s0 * 128 + lane * 4];
                    uint2 v1 = *(const uint2*)&h1[(long long)s1 * 128 + lane * 4];
                    uint2 v2 = *(const uint2*)&h1[(long long)s2 * 128 + lane * 4];
                    uint2 v3 = *(const uint2*)&h1[(long long)s3 * 128 + lane * 4];
                    float2 f;
                    f = __half22float2(*(__half2*)&v0.x); accA0.x += f.x; accA0.y += f.y;
                    f = __half22float2(*(__half2*)&v0.y); accA1.x += f.x; accA1.y += f.y;
                    f = __half22float2(*(__half2*)&v1.x); accB0.x += f.x; accB0.y += f.y;
                    f = __half22float2(*(__half2*)&v1.y); accB1.x += f.x; accB1.y += f.y;
                    f = __half22float2(*(__half2*)&v2.x); accA0.x += f.x; accA0.y += f.y;
                    f = __half22float2(*(__half2*)&v2.y); accA1.x += f.x; accA1.y += f.y;
                    f = __half22float2(*(__half2*)&v3.x); accB0.x += f.x; accB0.y += f.y;
                    f = __half22float2(*(__half2*)&v3.y); accB1.x += f.x; accB1.y += f.y;
                }
                for (; t < cnt; t++) {
                    int s = __shfl_sync(FULL, mysrc, t);
                    uint2 v = *(const uint2*)&h1[(long long)s * 128 + lane * 4];
                    float2 f;
                    f = __half22float2(*(__half2*)&v.x); accA0.x += f.x; accA0.y += f.y;
                    f = __half22float2(*(__half2*)&v.y); accA1.x += f.x; accA1.y += f.y;
                }
            }
            float dv = g_dinv[node];
            float4 sv;
            sv.x = fmaxf(fmaf(dv, accA0.x + accB0.x, b4.x), 0.f);
            sv.y = fmaxf(fmaf(dv, accA0.y + accB0.y, b4.y), 0.f);
            sv.z = fmaxf(fmaf(dv, accA1.x + accB1.x, b4.z), 0.f);
            sv.w = fmaxf(fmaf(dv, accA1.y + accB1.y, b4.w), 0.f);
            *(float4*)&Sa[wid][lane * 4] = sv;
            __syncwarp();
            ull acc2 = 0ull;
#pragma unroll
            for (int kp = 0; kp < 32; kp++) {
                int k = g2 * 64 + 2 * kp;
                ull a = *(const ull*)&Sa[wid][k];
                ull w = *(const ull*)&W2p[(k >> 1) * 32 + j * 2];
                fma2(acc2, a, w);
            }
            float part = unpack_sum(acc2);
            part += __shfl_xor_sync(FULL, part, 16);
            if (lane < 16)
                g_h2s[(long long)node * 16 + j] = part * dv;
            __syncwarp();
        }
    }
}

// Fused: per-node CSR gather-sum of h2s + bias + log-softmax -> out.
__global__ void node2_kernel(const float* __restrict__ b2,
                             float* __restrict__ out, int n) {
    int warpInBlock = threadIdx.x >> 5;
    int lane = threadIdx.x & 31;
    int node = blockIdx.x * (blockDim.x >> 5) + warpInBlock;
    if (node >= n) return;
    int f = lane & 15;
    int eo = lane >> 4;
    int beg = g_row_ptr[node];
    int end = g_row_ptr[node + 1];
    float acc = 0.f;
    for (int e = beg + eo; e < end; e += 2) {
        int s = g_csr_src[e];
        acc += g_h2s[(long long)s * 16 + f];
    }
    acc += __shfl_xor_sync(0xffffffffu, acc, 16);
    float v = fmaf(g_dinv[node], acc, b2[f]);
    float mx = v;
#pragma unroll
    for (int off = 8; off >= 1; off >>= 1)
        mx = fmaxf(mx, __shfl_xor_sync(0xffffffffu, mx, off));
    float ex = expf(v - mx);
#pragma unroll
    for (int off = 8; off >= 1; off >>= 1)
        ex += __shfl_xor_sync(0xffffffffu, ex, off);
    float lse = mx + logf(ex);
    if (lane < 16)
        out[(long long)node * 16 + f] = v - lse;
}

// ---------------- launch ----------------
extern "C" void kernel_launch(void* const* d_in, const int* in_sizes, int n_in,
                              void* d_out, int out_size) {
    const float* x  = (const float*)d_in[0];
    const void*  ei = d_in[1];
    const float* W1 = (const float*)d_in[2];
    const float* b1 = (const float*)d_in[3];
    const float* W2 = (const float*)d_in[4];
    const float* b2 = (const float*)d_in[5];
    float* out = (float*)d_out;

    long long E = (long long)in_sizes[1] / 2;
    int n = in_sizes[0] / F1;
    int nScanBlocks = (n + 1023) / 1024;

    zero_detect_kernel<<<(n + 255) / 256, 256>>>(ei, n);
    deg_kernel<<<(int)((E + 255) / 256), 256>>>(ei, E);
    scan1_kernel<<<nScanBlocks, 1024>>>(n);
    scan2_kernel<<<nScanBlocks, 1024>>>(n, nScanBlocks);
    fill_kernel<<<(int)((E + 255) / 256), 256>>>(ei, E);
    gemm1_kernel<<<(n + 63) / 64, 256>>>(x, W1, n);
    node1_kernel<<<(n + NPB - 1) / NPB, 128>>>(b1, W2, n);
    node2_kernel<<<(n + 7) / 8, 256>>>(b2, out, n);
}

// round 11
// speedup vs baseline: 1.7402x; 1.0057x over previous
#include <cuda_runtime.h>
#include <cuda_fp16.h>
#include <cstdint>
#include <math.h>

#define MAXN 50000
#define MAXE 1000000
#define F1 128
#define F2 16

typedef unsigned long long ull;

// ---------------- device scratch ----------------
__device__ __align__(256) float  g_dinv[MAXN];
__device__ __align__(256) __half g_h1s [MAXN * F1];  // fp16: raw x@W1 (no dinv)
__device__ __align__(256) __half g_h2s [MAXN * F2];  // fp16: dinv*(relu@W2)
__device__ __align__(256) int    g_deg_i[MAXN];
__device__ __align__(256) int    g_cursor[MAXN];
__device__ __align__(256) int    g_row_ptr[MAXN + 1];
__device__ __align__(256) int2   g_csr_sd[MAXE];     // {src, bits(dinv[src])}
__device__ __align__(256) int    g_bsum[64];
__device__ int g_is64;

// ---------------- helpers ----------------
__device__ __forceinline__ long long load_idx(const void* ei, long long i, int is64) {
    if (is64) return ((const long long*)ei)[i];
    return (long long)((const int*)ei)[i];
}

__device__ __forceinline__ void fma2(ull& d, ull a, ull b) {
    asm("fma.rn.f32x2 %0, %1, %2, %3;" : "=l"(d) : "l"(a), "l"(b), "l"(d));
}
__device__ __forceinline__ float unpack_sum(ull v) {
    float lo, hi;
    asm("mov.b64 {%0,%1}, %2;" : "=f"(lo), "=f"(hi) : "l"(v));
    return lo + hi;
}

// ---------------- kernels ----------------

__global__ void zero_detect_kernel(const void* ei, int n) {
    int i = blockIdx.x * blockDim.x + threadIdx.x;
    if (i < n) { g_deg_i[i] = 0; g_cursor[i] = 0; }
    if (blockIdx.x == 0 && threadIdx.x == 0) {
        const long long* p = (const long long*)ei;
        int ok = 1;
        for (int k = 0; k < 8; k++) {
            long long v = p[k];
            if (v < 0 || v >= n) ok = 0;
        }
        g_is64 = ok;
    }
}

__global__ void deg_kernel(const void* ei, long long E) {
    long long i = (long long)blockIdx.x * blockDim.x + threadIdx.x;
    if (i >= E) return;
    int d = (int)load_idx(ei, E + i, g_is64);
    atomicAdd(&g_deg_i[d], 1);
}

__global__ void scan1_kernel(int n) {
    __shared__ int wsum[32];
    __shared__ int wexcl[32];
    const int tid = threadIdx.x, lane = tid & 31, wid = tid >> 5;
    int i = blockIdx.x * 1024 + tid;
    int d = (i < n) ? g_deg_i[i] : 0;
    int incl = d;
#pragma unroll
    for (int off = 1; off < 32; off <<= 1) {
        int t = __shfl_up_sync(0xffffffffu, incl, off);
        if (lane >= off) incl += t;
    }
    if (lane == 31) wsum[wid] = incl;
    __syncthreads();
    if (wid == 0) {
        int v = wsum[lane];
        int iv = v;
#pragma unroll
        for (int off = 1; off < 32; off <<= 1) {
            int t = __shfl_up_sync(0xffffffffu, iv, off);
            if (lane >= off) iv += t;
        }
        wexcl[lane] = iv - v;
    }
    __syncthreads();
    if (i < n) g_row_ptr[i] = wexcl[wid] + incl - d;
    if (tid == 1023) g_bsum[blockIdx.x] = wexcl[31] + incl;
}

__global__ void scan2_kernel(int n, int nblocks) {
    __shared__ int offset_s;
    const int tid = threadIdx.x;
    if (tid < 32) {
        int acc = 0;
        for (int j = tid; j < blockIdx.x; j += 32) acc += g_bsum[j];
#pragma unroll
        for (int off = 16; off >= 1; off >>= 1)
            acc += __shfl_xor_sync(0xffffffffu, acc, off);
        if (tid == 0) offset_s = acc;
    }
    __syncthreads();
    int i = blockIdx.x * 1024 + tid;
    if (i < n) {
        g_row_ptr[i] += offset_s;
        int d = g_deg_i[i];
        g_dinv[i] = rsqrtf((float)(d > 0 ? d : 1));
    }
    if ((int)blockIdx.x == nblocks - 1 && tid == 0)
        g_row_ptr[n] = offset_s + g_bsum[blockIdx.x];
}

// Build CSR pairs {src, dinv[src]}.
__global__ void fill_kernel(const void* ei, long long E) {
    long long i = (long long)blockIdx.x * blockDim.x + threadIdx.x;
    if (i >= E) return;
    int is64 = g_is64;
    int s = (int)load_idx(ei, i, is64);
    int d = (int)load_idx(ei, E + i, is64);
    int p = atomicAdd(&g_cursor[d], 1);
    g_csr_sd[g_row_ptr[d] + p] = make_int2(s, __float_as_int(g_dinv[s]));
}

// h1s = fp16(x @ W1). Independent of edge prep (runs on side stream).
__global__ void gemm1_kernel(const float* __restrict__ x,
                             const float* __restrict__ W1, int n) {
    __shared__ float Xs[64][36];
    __shared__ float Wkp[16 * 256];
    const int tid = threadIdx.x;
    const int tr = tid >> 4;
    const int tc = tid & 15;
    const int row0 = blockIdx.x * 64;

    ull acc2[4][8];
#pragma unroll
    for (int r = 0; r < 4; r++)
#pragma unroll
        for (int j = 0; j < 8; j++) acc2[r][j] = 0ull;

    for (int k0 = 0; k0 < 128; k0 += 32) {
#pragma unroll
        for (int i = tid; i < 512; i += 256) {
            int r = i >> 3, c4 = i & 7;
            int grow = row0 + r;
            float4 v = make_float4(0.f, 0.f, 0.f, 0.f);
            if (grow < n)
                v = *(const float4*)&x[(long long)grow * 128 + k0 + c4 * 4];
            *(float4*)&Xs[r][c4 * 4] = v;
        }
#pragma unroll
        for (int i = tid; i < 1024; i += 256) {
            int kr = i >> 5, c4 = i & 31;
            float4 v = *(const float4*)&W1[(long long)(k0 + kr) * 128 + c4 * 4];
            int base = (kr >> 1) * 256 + (kr & 1);
            Wkp[base + (c4 * 4 + 0) * 2] = v.x;
            Wkp[base + (c4 * 4 + 1) * 2] = v.y;
            Wkp[base + (c4 * 4 + 2) * 2] = v.z;
            Wkp[base + (c4 * 4 + 3) * 2] = v.w;
        }
        __syncthreads();
#pragma unroll
        for (int kp = 0; kp < 16; kp++) {
            ull a01[4];
#pragma unroll
            for (int r = 0; r < 4; r++)
                a01[r] = *(const ull*)&Xs[tr * 4 + r][2 * kp];
#pragma unroll
            for (int j = 0; j < 8; j++) {
                ull w = *(const ull*)&Wkp[kp * 256 + (tc + 16 * j) * 2];
#pragma unroll
                for (int r = 0; r < 4; r++) fma2(acc2[r][j], a01[r], w);
            }
        }
        __syncthreads();
    }
#pragma unroll
    for (int r = 0; r < 4; r++) {
        int grow = row0 + tr * 4 + r;
        if (grow < n) {
#pragma unroll
            for (int j = 0; j < 8; j++)
                g_h1s[(long long)grow * 128 + tc + 16 * j] =
                    __float2half(unpack_sum(acc2[r][j]));
        }
    }
}

// Fused: warp-per-node gather of fp16 h1s with per-edge dinv[src] FMA,
// relu+b1, @W2 (f32x2), *dinv[node] -> h2s (fp16).
#define NPB 8
__global__ void node1_kernel(const float* __restrict__ b1,
                             const float* __restrict__ W2, int n) {
    __shared__ float W2p[64 * 32];
    __shared__ float Sa[4][128];
    const int tid = threadIdx.x;
    const int wid = tid >> 5;
    const int lane = tid & 31;
    const unsigned FULL = 0xffffffffu;

    for (int i = tid; i < 2048; i += 128) {
        int k = i >> 4, j = i & 15;
        W2p[(k >> 1) * 32 + j * 2 + (k & 1)] = W2[i];
    }
    float4 b4 = ((const float4*)b1)[lane];
    __syncthreads();

    const int g2 = lane >> 4;
    const int j  = lane & 15;
    const __half* h1 = g_h1s;
    int node0 = blockIdx.x * NPB;

#pragma unroll
    for (int ch = 0; ch < 2; ch++) {
        int node = node0 + ch * 4 + wid;
        if (node < n) {
            int beg = g_row_ptr[node];
            int end = g_row_ptr[node + 1];
            float2 accA0 = make_float2(0.f, 0.f), accA1 = make_float2(0.f, 0.f);
            float2 accB0 = make_float2(0.f, 0.f), accB1 = make_float2(0.f, 0.f);
            for (int base = beg; base < end; base += 32) {
                int cnt = end - base; if (cnt > 32) cnt = 32;
                int idx = base + lane;
                int2 sd = (idx < end) ? g_csr_sd[idx] : make_int2(0, 0);
                int mysrc = sd.x;
                float mydv = __int_as_float(sd.y);
                int t = 0;
                for (; t + 4 <= cnt; t += 4) {
                    int s0 = __shfl_sync(FULL, mysrc, t);
                    float d0 = __shfl_sync(FULL, mydv, t);
                    int s1 = __shfl_sync(FULL, mysrc, t + 1);
                    float d1 = __shfl_sync(FULL, mydv, t + 1);
                    int s2 = __shfl_sync(FULL, mysrc, t + 2);
                    float d2 = __shfl_sync(FULL, mydv, t + 2);
                    int s3 = __shfl_sync(FULL, mysrc, t + 3);
                    float d3 = __shfl_sync(FULL, mydv, t + 3);
                    uint2 v0 = *(const uint2*)&h1[(long long)s0 * 128 + lane * 4];
                    uint2 v1 = *(const uint2*)&h1[(long long)s1 * 128 + lane * 4];
                    uint2 v2 = *(const uint2*)&h1[(long long)s2 * 128 + lane * 4];
                    uint2 v3 = *(const uint2*)&h1[(long long)s3 * 128 + lane * 4];
                    float2 f;
                    f = __half22float2(*(__half2*)&v0.x);
                    accA0.x = fmaf(d0, f.x, accA0.x); accA0.y = fmaf(d0, f.y, accA0.y);
                    f = __half22float2(*(__half2*)&v0.y);
                    accA1.x = fmaf(d0, f.x, accA1.x); accA1.y = fmaf(d0, f.y, accA1.y);
                    f = __half22float2(*(__half2*)&v1.x);
                    accB0.x = fmaf(d1, f.x, accB0.x); accB0.y = fmaf(d1, f.y, accB0.y);
                    f = __half22float2(*(__half2*)&v1.y);
                    accB1.x = fmaf(d1, f.x, accB1.x); accB1.y = fmaf(d1, f.y, accB1.y);
                    f = __half22float2(*(__half2*)&v2.x);
                    accA0.x = fmaf(d2, f.x, accA0.x); accA0.y = fmaf(d2, f.y, accA0.y);
                    f = __half22float2(*(__half2*)&v2.y);
                    accA1.x = fmaf(d2, f.x, accA1.x); accA1.y = fmaf(d2, f.y, accA1.y);
                    f = __half22float2(*(__half2*)&v3.x);
                    accB0.x = fmaf(d3, f.x, accB0.x); accB0.y = fmaf(d3, f.y, accB0.y);
                    f = __half22float2(*(__half2*)&v3.y);
                    accB1.x = fmaf(d3, f.x, accB1.x); accB1.y = fmaf(d3, f.y, accB1.y);
                }
                for (; t < cnt; t++) {
                    int s = __shfl_sync(FULL, mysrc, t);
                    float ds = __shfl_sync(FULL, mydv, t);
                    uint2 v = *(const uint2*)&h1[(long long)s * 128 + lane * 4];
                    float2 f;
                    f = __half22float2(*(__half2*)&v.x);
                    accA0.x = fmaf(ds, f.x, accA0.x); accA0.y = fmaf(ds, f.y, accA0.y);
                    f = __half22float2(*(__half2*)&v.y);
                    accA1.x = fmaf(ds, f.x, accA1.x); accA1.y = fmaf(ds, f.y, accA1.y);
                }
            }
            float dv = g_dinv[node];
            float4 sv;
            sv.x = fmaxf(fmaf(dv, accA0.x + accB0.x, b4.x), 0.f);
            sv.y = fmaxf(fmaf(dv, accA0.y + accB0.y, b4.y), 0.f);
            sv.z = fmaxf(fmaf(dv, accA1.x + accB1.x, b4.z), 0.f);
            sv.w = fmaxf(fmaf(dv, accA1.y + accB1.y, b4.w), 0.f);
            *(float4*)&Sa[wid][lane * 4] = sv;
            __syncwarp();
            ull acc2 = 0ull;
#pragma unroll
            for (int kp = 0; kp < 32; kp++) {
                int k = g2 * 64 + 2 * kp;
                ull a = *(const ull*)&Sa[wid][k];
                ull w = *(const ull*)&W2p[(k >> 1) * 32 + j * 2];
                fma2(acc2, a, w);
            }
            float part = unpack_sum(acc2);
            part += __shfl_xor_sync(FULL, part, 16);
            if (lane < 16)
                g_h2s[(long long)node * 16 + j] = __float2half(part * dv);
            __syncwarp();
        }
    }
}

// Warp per node. lane = eo*8 + fp: 4 edges in flight, fp = feature-pair.
__global__ void node2_kernel(const float* __restrict__ b2,
                             float* __restrict__ out, int n) {
    int warpInBlock = threadIdx.x >> 5;
    int lane = threadIdx.x & 31;
    int node = blockIdx.x * (blockDim.x >> 5) + warpInBlock;
    if (node >= n) return;
    const unsigned FULL = 0xffffffffu;
    int eo = lane >> 3;
    int fp = lane & 7;
    int beg = g_row_ptr[node];
    int end = g_row_ptr[node + 1];
    float2 acc = make_float2(0.f, 0.f);
    for (int e = beg + eo; e < end; e += 4) {
        int s = g_csr_sd[e].x;
        float2 f = __half22float2(*(const __half2*)&g_h2s[(long long)s * 16 + 2 * fp]);
        acc.x += f.x; acc.y += f.y;
    }
    acc.x += __shfl_xor_sync(FULL, acc.x, 8);
    acc.y += __shfl_xor_sync(FULL, acc.y, 8);
    acc.x += __shfl_xor_sync(FULL, acc.x, 16);
    acc.y += __shfl_xor_sync(FULL, acc.y, 16);
    float dv = g_dinv[node];
    float2 b = *(const float2*)&b2[2 * fp];
    float vx = fmaf(dv, acc.x, b.x);
    float vy = fmaf(dv, acc.y, b.y);
    float mx = fmaxf(vx, vy);
#pragma unroll
    for (int off = 4; off >= 1; off >>= 1)
        mx = fmaxf(mx, __shfl_xor_sync(FULL, mx, off));
    float ex = expf(vx - mx) + expf(vy - mx);
#pragma unroll
    for (int off = 4; off >= 1; off >>= 1)
        ex += __shfl_xor_sync(FULL, ex, off);
    float lse = mx + logf(ex);
    if (lane < 8) {
        float2 o = make_float2(vx - lse, vy - lse);
        *(float2*)&out[(long long)node * 16 + 2 * fp] = o;
    }
}

// ---------------- launch ----------------
extern "C" void kernel_launch(void* const* d_in, const int* in_sizes, int n_in,
                              void* d_out, int out_size) {
    const float* x  = (const float*)d_in[0];
    const void*  ei = d_in[1];
    const float* W1 = (const float*)d_in[2];
    const float* b1 = (const float*)d_in[3];
    const float* W2 = (const float*)d_in[4];
    const float* b2 = (const float*)d_in[5];
    float* out = (float*)d_out;

    long long E = (long long)in_sizes[1] / 2;
    int n = in_sizes[0] / F1;
    int nScanBlocks = (n + 1023) / 1024;

    static cudaStream_t s2 = nullptr;
    static cudaEvent_t evFork = nullptr, evJoin = nullptr;
    if (!s2) {
        cudaStreamCreateWithFlags(&s2, cudaStreamNonBlocking);
        cudaEventCreateWithFlags(&evFork, cudaEventDisableTiming);
        cudaEventCreateWithFlags(&evJoin, cudaEventDisableTiming);
    }

    // Fork: gemm1 (x@W1, no dinv) on side stream, overlapped with edge prep.
    cudaEventRecord(evFork, 0);
    cudaStreamWaitEvent(s2, evFork, 0);
    gemm1_kernel<<<(n + 63) / 64, 256, 0, s2>>>(x, W1, n);
    cudaEventRecord(evJoin, s2);

    // Edge-prep chain on main stream.
    zero_detect_kernel<<<(n + 255) / 256, 256>>>(ei, n);
    deg_kernel<<<(int)((E + 255) / 256), 256>>>(ei, E);
    scan1_kernel<<<nScanBlocks, 1024>>>(n);
    scan2_kernel<<<nScanBlocks, 1024>>>(n, nScanBlocks);
    fill_kernel<<<(int)((E + 255) / 256), 256>>>(ei, E);

    // Join, then fused node phases.
    cudaStreamWaitEvent(0, evJoin, 0);
    node1_kernel<<<(n + NPB - 1) / NPB, 128>>>(b1, W2, n);
    node2_kernel<<<(n + 7) / 8, 256>>>(b2, out, n);
}

// round 12
// speedup vs baseline: 2.2664x; 1.3024x over previous
#include <cuda_runtime.h>
#include <cuda_fp16.h>
#include <cstdint>
#include <math.h>

#define MAXN 50000
#define MAXE 1000000
#define F1 128
#define F2 16

typedef unsigned long long ull;
typedef unsigned int u32;

// ---------------- device scratch ----------------
__device__ __align__(256) float  g_dinv[MAXN];
__device__ __align__(256) __half g_h1s [MAXN * F1];  // fp16: raw x@W1 (no dinv)
__device__ __align__(256) __half g_h2s [MAXN * F2];  // fp16: dinv*(relu@W2)
__device__ __align__(256) int    g_deg_i[MAXN];
__device__ __align__(256) int    g_cursor[MAXN];
__device__ __align__(256) int    g_row_ptr[MAXN + 1];
__device__ __align__(256) int2   g_csr_sd[MAXE];     // {src, bits(dinv[src])}
__device__ __align__(256) int    g_bsum[64];
__device__ int g_is64;

// ---------------- helpers ----------------
__device__ __forceinline__ long long load_idx(const void* ei, long long i, int is64) {
    if (is64) return ((const long long*)ei)[i];
    return (long long)((const int*)ei)[i];
}
__device__ __forceinline__ void fma2(ull& d, ull a, ull b) {
    asm("fma.rn.f32x2 %0, %1, %2, %3;" : "=l"(d) : "l"(a), "l"(b), "l"(d));
}
__device__ __forceinline__ float unpack_sum(ull v) {
    float lo, hi;
    asm("mov.b64 {%0,%1}, %2;" : "=f"(lo), "=f"(hi) : "l"(v));
    return lo + hi;
}
__device__ __forceinline__ u32 smem_u32(const void* p) {
    return (u32)__cvta_generic_to_shared(p);
}
// Swizzles: XOR 16B-unit index with (row & 7). Conflict-free ldmatrix.
__device__ __forceinline__ u32 swA(u32 r, u32 b) {   // 128B rows
    return r * 128u + ((((b >> 4) ^ (r & 7u)) << 4) | (b & 15u));
}
__device__ __forceinline__ u32 swB(u32 r, u32 b) {   // 256B rows
    return r * 256u + ((((b >> 4) ^ (r & 7u)) << 4) | (b & 15u));
}
__device__ __forceinline__ void ldsm4(u32& r0, u32& r1, u32& r2, u32& r3, u32 addr) {
    asm volatile("ldmatrix.sync.aligned.m8n8.x4.shared.b16 {%0,%1,%2,%3}, [%4];"
                 : "=r"(r0), "=r"(r1), "=r"(r2), "=r"(r3) : "r"(addr));
}
__device__ __forceinline__ void ldsm4t(u32& r0, u32& r1, u32& r2, u32& r3, u32 addr) {
    asm volatile("ldmatrix.sync.aligned.m8n8.x4.trans.shared.b16 {%0,%1,%2,%3}, [%4];"
                 : "=r"(r0), "=r"(r1), "=r"(r2), "=r"(r3) : "r"(addr));
}
__device__ __forceinline__ void mma16816(float* c, u32 a0, u32 a1, u32 a2, u32 a3,
                                         u32 b0, u32 b1) {
    asm volatile("mma.sync.aligned.m16n8k16.row.col.f32.f16.f16.f32 "
                 "{%0,%1,%2,%3}, {%4,%5,%6,%7}, {%8,%9}, {%0,%1,%2,%3};"
                 : "+f"(c[0]), "+f"(c[1]), "+f"(c[2]), "+f"(c[3])
                 : "r"(a0), "r"(a1), "r"(a2), "r"(a3), "r"(b0), "r"(b1));
}

// ---------------- kernels ----------------

__global__ void zero_detect_kernel(const void* ei, int n) {
    int i = blockIdx.x * blockDim.x + threadIdx.x;
    if (i < n) { g_deg_i[i] = 0; g_cursor[i] = 0; }
    if (blockIdx.x == 0 && threadIdx.x == 0) {
        const long long* p = (const long long*)ei;
        int ok = 1;
        for (int k = 0; k < 8; k++) {
            long long v = p[k];
            if (v < 0 || v >= n) ok = 0;
        }
        g_is64 = ok;
    }
}

__global__ void deg_kernel(const void* ei, long long E) {
    long long i = (long long)blockIdx.x * blockDim.x + threadIdx.x;
    if (i >= E) return;
    int d = (int)load_idx(ei, E + i, g_is64);
    atomicAdd(&g_deg_i[d], 1);
}

__global__ void scan1_kernel(int n) {
    __shared__ int wsum[32];
    __shared__ int wexcl[32];
    const int tid = threadIdx.x, lane = tid & 31, wid = tid >> 5;
    int i = blockIdx.x * 1024 + tid;
    int d = (i < n) ? g_deg_i[i] : 0;
    int incl = d;
#pragma unroll
    for (int off = 1; off < 32; off <<= 1) {
        int t = __shfl_up_sync(0xffffffffu, incl, off);
        if (lane >= off) incl += t;
    }
    if (lane == 31) wsum[wid] = incl;
    __syncthreads();
    if (wid == 0) {
        int v = wsum[lane];
        int iv = v;
#pragma unroll
        for (int off = 1; off < 32; off <<= 1) {
            int t = __shfl_up_sync(0xffffffffu, iv, off);
            if (lane >= off) iv += t;
        }
        wexcl[lane] = iv - v;
    }
    __syncthreads();
    if (i < n) g_row_ptr[i] = wexcl[wid] + incl - d;
    if (tid == 1023) g_bsum[blockIdx.x] = wexcl[31] + incl;
}

__global__ void scan2_kernel(int n, int nblocks) {
    __shared__ int offset_s;
    const int tid = threadIdx.x;
    if (tid < 32) {
        int acc = 0;
        for (int j = tid; j < blockIdx.x; j += 32) acc += g_bsum[j];
#pragma unroll
        for (int off = 16; off >= 1; off >>= 1)
            acc += __shfl_xor_sync(0xffffffffu, acc, off);
        if (tid == 0) offset_s = acc;
    }
    __syncthreads();
    int i = blockIdx.x * 1024 + tid;
    if (i < n) {
        g_row_ptr[i] += offset_s;
        int d = g_deg_i[i];
        g_dinv[i] = rsqrtf((float)(d > 0 ? d : 1));
    }
    if ((int)blockIdx.x == nblocks - 1 && tid == 0)
        g_row_ptr[n] = offset_s + g_bsum[blockIdx.x];
}

__global__ void fill_kernel(const void* ei, long long E) {
    long long i = (long long)blockIdx.x * blockDim.x + threadIdx.x;
    if (i >= E) return;
    int is64 = g_is64;
    int s = (int)load_idx(ei, i, is64);
    int d = (int)load_idx(ei, E + i, is64);
    int p = atomicAdd(&g_cursor[d], 1);
    g_csr_sd[g_row_ptr[d] + p] = make_int2(s, __float_as_int(g_dinv[s]));
}

// h1s = fp16(x @ W1) via HMMA (mma.sync m16n8k16).
// BM=128, BN=128, K in two 64-chunks. 256 thr = 8 warps (2 M x 4 N),
// warp tile 64x32. fp32 inputs converted to fp16 in smem.
__global__ void __launch_bounds__(256, 2)
gemm1_kernel(const float* __restrict__ x, const float* __restrict__ W1, int n) {
    __shared__ __half As[128 * 64];   // 128 rows x 64 halves (chunk of K)
    __shared__ __half Bs[64 * 128];   // 64 k-rows x 128 n-halves
    const int tid = threadIdx.x;
    const int warp = tid >> 5;
    const int lane = tid & 31;
    const int wm = warp >> 2;         // 0..1
    const int wn = warp & 3;          // 0..3
    const int row0 = blockIdx.x * 128;
    const u32 AsB = smem_u32(As);
    const u32 BsB = smem_u32(Bs);

    float acc[4][4][4];               // [mt][nt][frag]
#pragma unroll
    for (int mt = 0; mt < 4; mt++)
#pragma unroll
        for (int nt = 0; nt < 4; nt++)
#pragma unroll
            for (int q = 0; q < 4; q++) acc[mt][nt][q] = 0.f;

    const int sub = lane >> 3, rin = lane & 7;

#pragma unroll
    for (int kc = 0; kc < 2; kc++) {
        // Load A chunk: 128 rows x 16 float4 -> fp16 swizzled.
#pragma unroll
        for (int i = tid; i < 2048; i += 256) {
            int r = i >> 4, c4 = i & 15;
            int grow = row0 + r;
            float4 v = make_float4(0.f, 0.f, 0.f, 0.f);
            if (grow < n)
                v = *(const float4*)&x[(long long)grow * 128 + kc * 64 + c4 * 4];
            __half2 h01 = __floats2half2_rn(v.x, v.y);
            __half2 h23 = __floats2half2_rn(v.z, v.w);
            u32 off = swA(r, c4 * 8);
            *(__half2*)((char*)As + off)     = h01;
            *(__half2*)((char*)As + off + 4) = h23;
        }
        // Load B chunk: 64 k-rows x 32 float4 -> fp16 swizzled.
#pragma unroll
        for (int i = tid; i < 2048; i += 256) {
            int r = i >> 5, c4 = i & 31;
            float4 v = *(const float4*)&W1[(long long)(kc * 64 + r) * 128 + c4 * 4];
            __half2 h01 = __floats2half2_rn(v.x, v.y);
            __half2 h23 = __floats2half2_rn(v.z, v.w);
            u32 off = swB(r, c4 * 8);
            *(__half2*)((char*)Bs + off)     = h01;
            *(__half2*)((char*)Bs + off + 4) = h23;
        }
        __syncthreads();

#pragma unroll
        for (int kk = 0; kk < 4; kk++) {
            u32 af[4][4];
#pragma unroll
            for (int mt = 0; mt < 4; mt++) {
                u32 r = wm * 64 + mt * 16 + (sub & 1) * 8 + rin;
                u32 bcol = (kk * 16 + (sub >> 1) * 8) * 2;
                ldsm4(af[mt][0], af[mt][1], af[mt][2], af[mt][3], AsB + swA(r, bcol));
            }
            u32 bf[4][2];
#pragma unroll
            for (int ntp = 0; ntp < 2; ntp++) {
                u32 kr = kk * 16 + (sub & 1) * 8 + rin;
                u32 bcol = (wn * 32 + ntp * 16 + (sub >> 1) * 8) * 2;
                u32 r0, r1, r2, r3;
                ldsm4t(r0, r1, r2, r3, BsB + swB(kr, bcol));
                bf[ntp * 2][0] = r0; bf[ntp * 2][1] = r1;
                bf[ntp * 2 + 1][0] = r2; bf[ntp * 2 + 1][1] = r3;
            }
#pragma unroll
            for (int mt = 0; mt < 4; mt++)
#pragma unroll
                for (int nt = 0; nt < 4; nt++)
                    mma16816(acc[mt][nt], af[mt][0], af[mt][1], af[mt][2], af[mt][3],
                             bf[nt][0], bf[nt][1]);
        }
        __syncthreads();
    }

    // Epilogue: fragment layout -> fp16 h1s.
    const int g = lane >> 2, tg = lane & 3;
#pragma unroll
    for (int mt = 0; mt < 4; mt++) {
        int r0g = row0 + wm * 64 + mt * 16 + g;
#pragma unroll
        for (int nt = 0; nt < 4; nt++) {
            int col = wn * 32 + nt * 8 + tg * 2;
            if (r0g < n)
                *(__half2*)&g_h1s[(long long)r0g * 128 + col] =
                    __floats2half2_rn(acc[mt][nt][0], acc[mt][nt][1]);
            if (r0g + 8 < n)
                *(__half2*)&g_h1s[(long long)(r0g + 8) * 128 + col] =
                    __floats2half2_rn(acc[mt][nt][2], acc[mt][nt][3]);
        }
    }
}

// Fused: warp-per-node gather of fp16 h1s with per-edge dinv[src] FMA,
// relu+b1, @W2 (f32x2), *dinv[node] -> h2s (fp16).
#define NPB 8
__global__ void node1_kernel(const float* __restrict__ b1,
                             const float* __restrict__ W2, int n) {
    __shared__ float W2p[64 * 32];
    __shared__ float Sa[4][128];
    const int tid = threadIdx.x;
    const int wid = tid >> 5;
    const int lane = tid & 31;
    const unsigned FULL = 0xffffffffu;

    for (int i = tid; i < 2048; i += 128) {
        int k = i >> 4, j = i & 15;
        W2p[(k >> 1) * 32 + j * 2 + (k & 1)] = W2[i];
    }
    float4 b4 = ((const float4*)b1)[lane];
    __syncthreads();

    const int g2 = lane >> 4;
    const int j  = lane & 15;
    const __half* h1 = g_h1s;
    int node0 = blockIdx.x * NPB;

#pragma unroll
    for (int ch = 0; ch < 2; ch++) {
        int node = node0 + ch * 4 + wid;
        if (node < n) {
            int beg = g_row_ptr[node];
            int end = g_row_ptr[node + 1];
            float2 accA0 = make_float2(0.f, 0.f), accA1 = make_float2(0.f, 0.f);
            float2 accB0 = make_float2(0.f, 0.f), accB1 = make_float2(0.f, 0.f);
            for (int base = beg; base < end; base += 32) {
                int cnt = end - base; if (cnt > 32) cnt = 32;
                int idx = base + lane;
                int2 sd = (idx < end) ? g_csr_sd[idx] : make_int2(0, 0);
                int mysrc = sd.x;
                float mydv = __int_as_float(sd.y);
                int t = 0;
                for (; t + 4 <= cnt; t += 4) {
                    int s0 = __shfl_sync(FULL, mysrc, t);
                    float d0 = __shfl_sync(FULL, mydv, t);
                    int s1 = __shfl_sync(FULL, mysrc, t + 1);
                    float d1 = __shfl_sync(FULL, mydv, t + 1);
                    int s2 = __shfl_sync(FULL, mysrc, t + 2);
                    float d2 = __shfl_sync(FULL, mydv, t + 2);
                    int s3 = __shfl_sync(FULL, mysrc, t + 3);
                    float d3 = __shfl_sync(FULL, mydv, t + 3);
                    uint2 v0 = *(const uint2*)&h1[(long long)s0 * 128 + lane * 4];
                    uint2 v1 = *(const uint2*)&h1[(long long)s1 * 128 + lane * 4];
                    uint2 v2 = *(const uint2*)&h1[(long long)s2 * 128 + lane * 4];
                    uint2 v3 = *(const uint2*)&h1[(long long)s3 * 128 + lane * 4];
                    float2 f;
                    f = __half22float2(*(__half2*)&v0.x);
                    accA0.x = fmaf(d0, f.x, accA0.x); accA0.y = fmaf(d0, f.y, accA0.y);
                    f = __half22float2(*(__half2*)&v0.y);
                    accA1.x = fmaf(d0, f.x, accA1.x); accA1.y = fmaf(d0, f.y, accA1.y);
                    f = __half22float2(*(__half2*)&v1.x);
                    accB0.x = fmaf(d1, f.x, accB0.x); accB0.y = fmaf(d1, f.y, accB0.y);
                    f = __half22float2(*(__half2*)&v1.y);
                    accB1.x = fmaf(d1, f.x, accB1.x); accB1.y = fmaf(d1, f.y, accB1.y);
                    f = __half22float2(*(__half2*)&v2.x);
                    accA0.x = fmaf(d2, f.x, accA0.x); accA0.y = fmaf(d2, f.y, accA0.y);
                    f = __half22float2(*(__half2*)&v2.y);
                    accA1.x = fmaf(d2, f.x, accA1.x); accA1.y = fmaf(d2, f.y, accA1.y);
                    f = __half22float2(*(__half2*)&v3.x);
                    accB0.x = fmaf(d3, f.x, accB0.x); accB0.y = fmaf(d3, f.y, accB0.y);
                    f = __half22float2(*(__half2*)&v3.y);
                    accB1.x = fmaf(d3, f.x, accB1.x); accB1.y = fmaf(d3, f.y, accB1.y);
                }
                for (; t < cnt; t++) {
                    int s = __shfl_sync(FULL, mysrc, t);
                    float ds = __shfl_sync(FULL, mydv, t);
                    uint2 v = *(const uint2*)&h1[(long long)s * 128 + lane * 4];
                    float2 f;
                    f = __half22float2(*(__half2*)&v.x);
                    accA0.x = fmaf(ds, f.x, accA0.x); accA0.y = fmaf(ds, f.y, accA0.y);
                    f = __half22float2(*(__half2*)&v.y);
                    accA1.x = fmaf(ds, f.x, accA1.x); accA1.y = fmaf(ds, f.y, accA1.y);
                }
            }
            float dv = g_dinv[node];
            float4 sv;
            sv.x = fmaxf(fmaf(dv, accA0.x + accB0.x, b4.x), 0.f);
            sv.y = fmaxf(fmaf(dv, accA0.y + accB0.y, b4.y), 0.f);
            sv.z = fmaxf(fmaf(dv, accA1.x + accB1.x, b4.z), 0.f);
            sv.w = fmaxf(fmaf(dv, accA1.y + accB1.y, b4.w), 0.f);
            *(float4*)&Sa[wid][lane * 4] = sv;
            __syncwarp();
            ull acc2 = 0ull;
#pragma unroll
            for (int kp = 0; kp < 32; kp++) {
                int k = g2 * 64 + 2 * kp;
                ull a = *(const ull*)&Sa[wid][k];
                ull w = *(const ull*)&W2p[(k >> 1) * 32 + j * 2];
                fma2(acc2, a, w);
            }
            float part = unpack_sum(acc2);
            part += __shfl_xor_sync(FULL, part, 16);
            if (lane < 16)
                g_h2s[(long long)node * 16 + j] = __float2half(part * dv);
            __syncwarp();
        }
    }
}

// Warp per node. lane = eo*8 + fp: 4 edges in flight, fp = feature-pair.
__global__ void node2_kernel(const float* __restrict__ b2,
                             float* __restrict__ out, int n) {
    int warpInBlock = threadIdx.x >> 5;
    int lane = threadIdx.x & 31;
    int node = blockIdx.x * (blockDim.x >> 5) + warpInBlock;
    if (node >= n) return;
    const unsigned FULL = 0xffffffffu;
    int eo = lane >> 3;
    int fp = lane & 7;
    int beg = g_row_ptr[node];
    int end = g_row_ptr[node + 1];
    float2 acc = make_float2(0.f, 0.f);
    for (int e = beg + eo; e < end; e += 4) {
        int s = g_csr_sd[e].x;
        float2 f = __half22float2(*(const __half2*)&g_h2s[(long long)s * 16 + 2 * fp]);
        acc.x += f.x; acc.y += f.y;
    }
    acc.x += __shfl_xor_sync(FULL, acc.x, 8);
    acc.y += __shfl_xor_sync(FULL, acc.y, 8);
    acc.x += __shfl_xor_sync(FULL, acc.x, 16);
    acc.y += __shfl_xor_sync(FULL, acc.y, 16);
    float dv = g_dinv[node];
    float2 b = *(const float2*)&b2[2 * fp];
    float vx = fmaf(dv, acc.x, b.x);
    float vy = fmaf(dv, acc.y, b.y);
    float mx = fmaxf(vx, vy);
#pragma unroll
    for (int off = 4; off >= 1; off >>= 1)
        mx = fmaxf(mx, __shfl_xor_sync(FULL, mx, off));
    float ex = expf(vx - mx) + expf(vy - mx);
#pragma unroll
    for (int off = 4; off >= 1; off >>= 1)
        ex += __shfl_xor_sync(FULL, ex, off);
    float lse = mx + logf(ex);
    if (lane < 8) {
        float2 o = make_float2(vx - lse, vy - lse);
        *(float2*)&out[(long long)node * 16 + 2 * fp] = o;
    }
}

// ---------------- launch ----------------
extern "C" void kernel_launch(void* const* d_in, const int* in_sizes, int n_in,
                              void* d_out, int out_size) {
    const float* x  = (const float*)d_in[0];
    const void*  ei = d_in[1];
    const float* W1 = (const float*)d_in[2];
    const float* b1 = (const float*)d_in[3];
    const float* W2 = (const float*)d_in[4];
    const float* b2 = (const float*)d_in[5];
    float* out = (float*)d_out;

    long long E = (long long)in_sizes[1] / 2;
    int n = in_sizes[0] / F1;
    int nScanBlocks = (n + 1023) / 1024;

    static cudaStream_t s2 = nullptr;
    static cudaEvent_t evFork = nullptr, evJoin = nullptr;
    if (!s2) {
        cudaStreamCreateWithFlags(&s2, cudaStreamNonBlocking);
        cudaEventCreateWithFlags(&evFork, cudaEventDisableTiming);
        cudaEventCreateWithFlags(&evJoin, cudaEventDisableTiming);
    }

    // Fork: tensor-core gemm1 on side stream, overlapped with edge prep.
    cudaEventRecord(evFork, 0);
    cudaStreamWaitEvent(s2, evFork, 0);
    gemm1_kernel<<<(n + 127) / 128, 256, 0, s2>>>(x, W1, n);
    cudaEventRecord(evJoin, s2);

    // Edge-prep chain on main stream.
    zero_detect_kernel<<<(n + 255) / 256, 256>>>(ei, n);
    deg_kernel<<<(int)((E + 255) / 256), 256>>>(ei, E);
    scan1_kernel<<<nScanBlocks, 1024>>>(n);
    scan2_kernel<<<nScanBlocks, 1024>>>(n, nScanBlocks);
    fill_kernel<<<(int)((E + 255) / 256), 256>>>(ei, E);

    // Join, then fused node phases.
    cudaStreamWaitEvent(0, evJoin, 0);
    node1_kernel<<<(n + NPB - 1) / NPB, 128>>>(b1, W2, n);
    node2_kernel<<<(n + 7) / 8, 256>>>(b2, out, n);
}

// round 14
// speedup vs baseline: 2.3345x; 1.0301x over previous
#include <cuda_runtime.h>
#include <cuda_fp16.h>
#include <cstdint>
#include <math.h>

#define MAXN 50000
#define MAXE 1000000
#define F1 128
#define F2 16

typedef unsigned long long ull;
typedef unsigned int u32;

// ---------------- device scratch ----------------
__device__ __align__(256) float  g_dinv[MAXN];
__device__ __align__(256) __half g_h1s [MAXN * F1];  // fp16: raw x@W1 (no dinv)
__device__ __align__(256) __half g_h2s [MAXN * F2];  // fp16: dinv*(relu@W2)
__device__ __align__(256) int    g_deg_i[MAXN];
__device__ __align__(256) int    g_cursor[MAXN];
__device__ __align__(256) int    g_row_ptr[MAXN + 1];
__device__ __align__(256) int2   g_csr_sd[MAXE];     // {src, bits(dinv[src])}
__device__ __align__(256) int    g_csr_src[MAXE];    // src only (node2 path)
__device__ __align__(256) int    g_bsum[64];
__device__ int g_is64;

// ---------------- helpers ----------------
__device__ __forceinline__ long long load_idx(const void* ei, long long i, int is64) {
    if (is64) return ((const long long*)ei)[i];
    return (long long)((const int*)ei)[i];
}
__device__ __forceinline__ void fma2(ull& d, ull a, ull b) {
    asm("fma.rn.f32x2 %0, %1, %2, %3;" : "=l"(d) : "l"(a), "l"(b), "l"(d));
}
__device__ __forceinline__ float unpack_sum(ull v) {
    float lo, hi;
    asm("mov.b64 {%0,%1}, %2;" : "=f"(lo), "=f"(hi) : "l"(v));
    return lo + hi;
}
__device__ __forceinline__ u32 smem_u32(const void* p) {
    return (u32)__cvta_generic_to_shared(p);
}
__device__ __forceinline__ u32 swA(u32 r, u32 b) {
    return r * 128u + ((((b >> 4) ^ (r & 7u)) << 4) | (b & 15u));
}
__device__ __forceinline__ u32 swB(u32 r, u32 b) {
    return r * 256u + ((((b >> 4) ^ (r & 7u)) << 4) | (b & 15u));
}
__device__ __forceinline__ void ldsm4(u32& r0, u32& r1, u32& r2, u32& r3, u32 addr) {
    asm volatile("ldmatrix.sync.aligned.m8n8.x4.shared.b16 {%0,%1,%2,%3}, [%4];"
                 : "=r"(r0), "=r"(r1), "=r"(r2), "=r"(r3) : "r"(addr));
}
__device__ __forceinline__ void ldsm4t(u32& r0, u32& r1, u32& r2, u32& r3, u32 addr) {
    asm volatile("ldmatrix.sync.aligned.m8n8.x4.trans.shared.b16 {%0,%1,%2,%3}, [%4];"
                 : "=r"(r0), "=r"(r1), "=r"(r2), "=r"(r3) : "r"(addr));
}
__device__ __forceinline__ void mma16816(float* c, u32 a0, u32 a1, u32 a2, u32 a3,
                                         u32 b0, u32 b1) {
    asm volatile("mma.sync.aligned.m16n8k16.row.col.f32.f16.f16.f32 "
                 "{%0,%1,%2,%3}, {%4,%5,%6,%7}, {%8,%9}, {%0,%1,%2,%3};"
                 : "+f"(c[0]), "+f"(c[1]), "+f"(c[2]), "+f"(c[3])
                 : "r"(a0), "r"(a1), "r"(a2), "r"(a3), "r"(b0), "r"(b1));
}

// One edge's contribution: gather 8 fp16 features, scale by d, accumulate.
__device__ __forceinline__ void edge_acc(const __half* h1, int s, float d, int ln,
                                         float2& p0, float2& p1,
                                         float2& p2, float2& p3) {
    uint4 v = *(const uint4*)&h1[(long long)s * 128 + ln * 8];
    float2 f;
    f = __half22float2(*(__half2*)&v.x);
    p0.x = fmaf(d, f.x, p0.x); p0.y = fmaf(d, f.y, p0.y);
    f = __half22float2(*(__half2*)&v.y);
    p1.x = fmaf(d, f.x, p1.x); p1.y = fmaf(d, f.y, p1.y);
    f = __half22float2(*(__half2*)&v.z);
    p2.x = fmaf(d, f.x, p2.x); p2.y = fmaf(d, f.y, p2.y);
    f = __half22float2(*(__half2*)&v.w);
    p3.x = fmaf(d, f.x, p3.x); p3.y = fmaf(d, f.y, p3.y);
}

// ---------------- kernels ----------------

__global__ void zero_detect_kernel(const void* ei, int n) {
    int i = blockIdx.x * blockDim.x + threadIdx.x;
    if (i < n) { g_deg_i[i] = 0; g_cursor[i] = 0; }
    if (blockIdx.x == 0 && threadIdx.x == 0) {
        const long long* p = (const long long*)ei;
        int ok = 1;
        for (int k = 0; k < 8; k++) {
            long long v = p[k];
            if (v < 0 || v >= n) ok = 0;
        }
        g_is64 = ok;
    }
}

__global__ void deg_kernel(const void* ei, long long E) {
    long long i = (long long)blockIdx.x * blockDim.x + threadIdx.x;
    if (i >= E) return;
    int d = (int)load_idx(ei, E + i, g_is64);
    atomicAdd(&g_deg_i[d], 1);
}

__global__ void scan1_kernel(int n) {
    __shared__ int wsum[32];
    __shared__ int wexcl[32];
    const int tid = threadIdx.x, lane = tid & 31, wid = tid >> 5;
    int i = blockIdx.x * 1024 + tid;
    int d = (i < n) ? g_deg_i[i] : 0;
    int incl = d;
#pragma unroll
    for (int off = 1; off < 32; off <<= 1) {
        int t = __shfl_up_sync(0xffffffffu, incl, off);
        if (lane >= off) incl += t;
    }
    if (lane == 31) wsum[wid] = incl;
    __syncthreads();
    if (wid == 0) {
        int v = wsum[lane];
        int iv = v;
#pragma unroll
        for (int off = 1; off < 32; off <<= 1) {
            int t = __shfl_up_sync(0xffffffffu, iv, off);
            if (lane >= off) iv += t;
        }
        wexcl[lane] = iv - v;
    }
    __syncthreads();
    if (i < n) g_row_ptr[i] = wexcl[wid] + incl - d;
    if (tid == 1023) g_bsum[blockIdx.x] = wexcl[31] + incl;
}

__global__ void scan2_kernel(int n, int nblocks) {
    __shared__ int offset_s;
    const int tid = threadIdx.x;
    if (tid < 32) {
        int acc = 0;
        for (int j = tid; j < blockIdx.x; j += 32) acc += g_bsum[j];
#pragma unroll
        for (int off = 16; off >= 1; off >>= 1)
            acc += __shfl_xor_sync(0xffffffffu, acc, off);
        if (tid == 0) offset_s = acc;
    }
    __syncthreads();
    int i = blockIdx.x * 1024 + tid;
    if (i < n) {
        g_row_ptr[i] += offset_s;
        int d = g_deg_i[i];
        g_dinv[i] = rsqrtf((float)(d > 0 ? d : 1));
    }
    if ((int)blockIdx.x == nblocks - 1 && tid == 0)
        g_row_ptr[n] = offset_s + g_bsum[blockIdx.x];
}

__global__ void fill_kernel(const void* ei, long long E) {
    long long i = (long long)blockIdx.x * blockDim.x + threadIdx.x;
    if (i >= E) return;
    int is64 = g_is64;
    int s = (int)load_idx(ei, i, is64);
    int d = (int)load_idx(ei, E + i, is64);
    int p = atomicAdd(&g_cursor[d], 1);
    int pos = g_row_ptr[d] + p;
    g_csr_sd[pos] = make_int2(s, __float_as_int(g_dinv[s]));
    g_csr_src[pos] = s;
}

// h1s = fp16(x @ W1) via HMMA.
__global__ void __launch_bounds__(256, 2)
gemm1_kernel(const float* __restrict__ x, const float* __restrict__ W1, int n) {
    __shared__ __half As[128 * 64];
    __shared__ __half Bs[64 * 128];
    const int tid = threadIdx.x;
    const int warp = tid >> 5;
    const int lane = tid & 31;
    const int wm = warp >> 2;
    const int wn = warp & 3;
    const int row0 = blockIdx.x * 128;
    const u32 AsB = smem_u32(As);
    const u32 BsB = smem_u32(Bs);

    float acc[4][4][4];
#pragma unroll
    for (int mt = 0; mt < 4; mt++)
#pragma unroll
        for (int nt = 0; nt < 4; nt++)
#pragma unroll
            for (int q = 0; q < 4; q++) acc[mt][nt][q] = 0.f;

    const int sub = lane >> 3, rin = lane & 7;

#pragma unroll
    for (int kc = 0; kc < 2; kc++) {
#pragma unroll
        for (int i = tid; i < 2048; i += 256) {
            int r = i >> 4, c4 = i & 15;
            int grow = row0 + r;
            float4 v = make_float4(0.f, 0.f, 0.f, 0.f);
            if (grow < n)
                v = *(const float4*)&x[(long long)grow * 128 + kc * 64 + c4 * 4];
            __half2 h01 = __floats2half2_rn(v.x, v.y);
            __half2 h23 = __floats2half2_rn(v.z, v.w);
            u32 off = swA(r, c4 * 8);
            *(__half2*)((char*)As + off)     = h01;
            *(__half2*)((char*)As + off + 4) = h23;
        }
#pragma unroll
        for (int i = tid; i < 2048; i += 256) {
            int r = i >> 5, c4 = i & 31;
            float4 v = *(const float4*)&W1[(long long)(kc * 64 + r) * 128 + c4 * 4];
            __half2 h01 = __floats2half2_rn(v.x, v.y);
            __half2 h23 = __floats2half2_rn(v.z, v.w);
            u32 off = swB(r, c4 * 8);
            *(__half2*)((char*)Bs + off)     = h01;
            *(__half2*)((char*)Bs + off + 4) = h23;
        }
        __syncthreads();

#pragma unroll
        for (int kk = 0; kk < 4; kk++) {
            u32 af[4][4];
#pragma unroll
            for (int mt = 0; mt < 4; mt++) {
                u32 r = wm * 64 + mt * 16 + (sub & 1) * 8 + rin;
                u32 bcol = (kk * 16 + (sub >> 1) * 8) * 2;
                ldsm4(af[mt][0], af[mt][1], af[mt][2], af[mt][3], AsB + swA(r, bcol));
            }
            u32 bf[4][2];
#pragma unroll
            for (int ntp = 0; ntp < 2; ntp++) {
                u32 kr = kk * 16 + (sub & 1) * 8 + rin;
                u32 bcol = (wn * 32 + ntp * 16 + (sub >> 1) * 8) * 2;
                u32 r0, r1, r2, r3;
                ldsm4t(r0, r1, r2, r3, BsB + swB(kr, bcol));
                bf[ntp * 2][0] = r0; bf[ntp * 2][1] = r1;
                bf[ntp * 2 + 1][0] = r2; bf[ntp * 2 + 1][1] = r3;
            }
#pragma unroll
            for (int mt = 0; mt < 4; mt++)
#pragma unroll
                for (int nt = 0; nt < 4; nt++)
                    mma16816(acc[mt][nt], af[mt][0], af[mt][1], af[mt][2], af[mt][3],
                             bf[nt][0], bf[nt][1]);
        }
        __syncthreads();
    }

    const int g = lane >> 2, tg = lane & 3;
#pragma unroll
    for (int mt = 0; mt < 4; mt++) {
        int r0g = row0 + wm * 64 + mt * 16 + g;
#pragma unroll
        for (int nt = 0; nt < 4; nt++) {
            int col = wn * 32 + nt * 8 + tg * 2;
            if (r0g < n)
                *(__half2*)&g_h1s[(long long)r0g * 128 + col] =
                    __floats2half2_rn(acc[mt][nt][0], acc[mt][nt][1]);
            if (r0g + 8 < n)
                *(__half2*)&g_h1s[(long long)(r0g + 8) * 128 + col] =
                    __floats2half2_rn(acc[mt][nt][2], acc[mt][nt][3]);
        }
    }
}

// node1: HALF-WARP per node. Lane ln (0..15) covers features [ln*8, ln*8+8)
// via one LDG.128 per edge. 2 nodes per warp in flight. W2: lane = output,
// no cross-lane reduce.
#define NPB 16
__global__ void node1_kernel(const float* __restrict__ b1,
                             const float* __restrict__ W2, int n) {
    __shared__ float W2p[64 * 32];          // [kp][j][2]
    __shared__ float Sa[8][132];            // per half-warp row
    const int tid = threadIdx.x;
    const int hw = tid >> 4;                // 0..7 half-warp id
    const int ln = tid & 15;
    const unsigned hmask = 0xFFFFu << (((tid >> 4) & 1) * 16);

    for (int i = tid; i < 2048; i += 128) {
        int k = i >> 4, j = i & 15;
        W2p[(k >> 1) * 32 + j * 2 + (k & 1)] = W2[i];
    }
    float4 blo = *(const float4*)&b1[ln * 8];
    float4 bhi = *(const float4*)&b1[ln * 8 + 4];
    __syncthreads();

    const __half* h1 = g_h1s;
    int node0 = blockIdx.x * NPB;

#pragma unroll 1
    for (int pass = 0; pass < 2; pass++) {
        int node = node0 + pass * 8 + hw;
        if (node < n) {
            int beg = g_row_ptr[node];
            int end = g_row_ptr[node + 1];
            // 8 features per lane: 2 ILP sets of 4 float2 accumulators
            float2 aA0 = make_float2(0.f,0.f), aA1 = aA0, aA2 = aA0, aA3 = aA0;
            float2 aB0 = aA0, aB1 = aA0, aB2 = aA0, aB3 = aA0;
#pragma unroll 1
            for (int base = beg; base < end; base += 32) {
                int i0 = base + ln, i1 = base + 16 + ln;
                int2 sd0 = (i0 < end) ? g_csr_sd[i0] : make_int2(0, 0);
                int2 sd1 = (i1 < end) ? g_csr_sd[i1] : make_int2(0, 0);
                float dv0 = __int_as_float(sd0.y);
                float dv1 = __int_as_float(sd1.y);
                int cnt = end - base; if (cnt > 32) cnt = 32;
                int c0 = cnt < 16 ? cnt : 16;
                int c1 = cnt - c0;
                int t = 0;
                for (; t + 2 <= c0; t += 2) {
                    int s  = __shfl_sync(hmask, sd0.x, t, 16);
                    float d = __shfl_sync(hmask, dv0, t, 16);
                    int s2 = __shfl_sync(hmask, sd0.x, t + 1, 16);
                    float d2 = __shfl_sync(hmask, dv0, t + 1, 16);
                    edge_acc(h1, s, d, ln, aA0, aA1, aA2, aA3);
                    edge_acc(h1, s2, d2, ln, aB0, aB1, aB2, aB3);
                }
                for (; t < c0; t++) {
                    int s = __shfl_sync(hmask, sd0.x, t, 16);
                    float d = __shfl_sync(hmask, dv0, t, 16);
                    edge_acc(h1, s, d, ln, aA0, aA1, aA2, aA3);
                }
                t = 0;
                for (; t + 2 <= c1; t += 2) {
                    int s  = __shfl_sync(hmask, sd1.x, t, 16);
                    float d = __shfl_sync(hmask, dv1, t, 16);
                    int s2 = __shfl_sync(hmask, sd1.x, t + 1, 16);
                    float d2 = __shfl_sync(hmask, dv1, t + 1, 16);
                    edge_acc(h1, s, d, ln, aA0, aA1, aA2, aA3);
                    edge_acc(h1, s2, d2, ln, aB0, aB1, aB2, aB3);
                }
                for (; t < c1; t++) {
                    int s = __shfl_sync(hmask, sd1.x, t, 16);
                    float d = __shfl_sync(hmask, dv1, t, 16);
                    edge_acc(h1, s, d, ln, aA0, aA1, aA2, aA3);
                }
            }
            float dv = g_dinv[node];
            float4 s0, s1;
            s0.x = fmaxf(fmaf(dv, aA0.x + aB0.x, blo.x), 0.f);
            s0.y = fmaxf(fmaf(dv, aA0.y + aB0.y, blo.y), 0.f);
            s0.z = fmaxf(fmaf(dv, aA1.x + aB1.x, blo.z), 0.f);
            s0.w = fmaxf(fmaf(dv, aA1.y + aB1.y, blo.w), 0.f);
            s1.x = fmaxf(fmaf(dv, aA2.x + aB2.x, bhi.x), 0.f);
            s1.y = fmaxf(fmaf(dv, aA2.y + aB2.y, bhi.y), 0.f);
            s1.z = fmaxf(fmaf(dv, aA3.x + aB3.x, bhi.z), 0.f);
            s1.w = fmaxf(fmaf(dv, aA3.y + aB3.y, bhi.w), 0.f);
            *(float4*)&Sa[hw][ln * 8]     = s0;
            *(float4*)&Sa[hw][ln * 8 + 4] = s1;
            __syncwarp(hmask);
            // W2: lane ln = output class ln, full k=128 via 64 fma2.
            ull acc2 = 0ull;
#pragma unroll
            for (int kp = 0; kp < 64; kp++) {
                ull a = *(const ull*)&Sa[hw][2 * kp];
                ull w = *(const ull*)&W2p[kp * 32 + ln * 2];
                fma2(acc2, a, w);
            }
            g_h2s[(long long)node * 16 + ln] = __float2half(unpack_sum(acc2) * dv);
            __syncwarp(hmask);
        }
    }
}

// Warp per node. lane = eo*8 + fp: 4 edges in flight, fp = feature-pair.
__global__ void node2_kernel(const float* __restrict__ b2,
                             float* __restrict__ out, int n) {
    int warpInBlock = threadIdx.x >> 5;
    int lane = threadIdx.x & 31;
    int node = blockIdx.x * (blockDim.x >> 5) + warpInBlock;
    if (node >= n) return;
    const unsigned FULL = 0xffffffffu;
    int eo = lane >> 3;
    int fp = lane & 7;
    int beg = g_row_ptr[node];
    int end = g_row_ptr[node + 1];
    float2 acc = make_float2(0.f, 0.f);
    for (int e = beg + eo; e < end; e += 4) {
        int s = g_csr_src[e];
        float2 f = __half22float2(*(const __half2*)&g_h2s[(long long)s * 16 + 2 * fp]);
        acc.x += f.x; acc.y += f.y;
    }
    acc.x += __shfl_xor_sync(FULL, acc.x, 8);
    acc.y += __shfl_xor_sync(FULL, acc.y, 8);
    acc.x += __shfl_xor_sync(FULL, acc.x, 16);
    acc.y += __shfl_xor_sync(FULL, acc.y, 16);
    float dv = g_dinv[node];
    float2 b = *(const float2*)&b2[2 * fp];
    float vx = fmaf(dv, acc.x, b.x);
    float vy = fmaf(dv, acc.y, b.y);
    float mx = fmaxf(vx, vy);
#pragma unroll
    for (int off = 4; off >= 1; off >>= 1)
        mx = fmaxf(mx, __shfl_xor_sync(FULL, mx, off));
    float ex = expf(vx - mx) + expf(vy - mx);
#pragma unroll
    for (int off = 4; off >= 1; off >>= 1)
        ex += __shfl_xor_sync(FULL, ex, off);
    float lse = mx + logf(ex);
    if (lane < 8) {
        float2 o = make_float2(vx - lse, vy - lse);
        *(float2*)&out[(long long)node * 16 + 2 * fp] = o;
    }
}

// ---------------- launch ----------------
extern "C" void kernel_launch(void* const* d_in, const int* in_sizes, int n_in,
                              void* d_out, int out_size) {
    const float* x  = (const float*)d_in[0];
    const void*  ei = d_in[1];
    const float* W1 = (const float*)d_in[2];
    const float* b1 = (const float*)d_in[3];
    const float* W2 = (const float*)d_in[4];
    const float* b2 = (const float*)d_in[5];
    float* out = (float*)d_out;

    long long E = (long long)in_sizes[1] / 2;
    int n = in_sizes[0] / F1;
    int nScanBlocks = (n + 1023) / 1024;

    static cudaStream_t s2 = nullptr;
    static cudaEvent_t evFork = nullptr, evJoin = nullptr;
    if (!s2) {
        cudaStreamCreateWithFlags(&s2, cudaStreamNonBlocking);
        cudaEventCreateWithFlags(&evFork, cudaEventDisableTiming);
        cudaEventCreateWithFlags(&evJoin, cudaEventDisableTiming);
    }

    cudaEventRecord(evFork, 0);
    cudaStreamWaitEvent(s2, evFork, 0);
    gemm1_kernel<<<(n + 127) / 128, 256, 0, s2>>>(x, W1, n);
    cudaEventRecord(evJoin, s2);

    zero_detect_kernel<<<(n + 255) / 256, 256>>>(ei, n);
    deg_kernel<<<(int)((E + 255) / 256), 256>>>(ei, E);
    scan1_kernel<<<nScanBlocks, 1024>>>(n);
    scan2_kernel<<<nScanBlocks, 1024>>>(n, nScanBlocks);
    fill_kernel<<<(int)((E + 255) / 256), 256>>>(ei, E);

    cudaStreamWaitEvent(0, evJoin, 0);
    node1_kernel<<<(n + NPB - 1) / NPB, 128>>>(b1, W2, n);
    node2_kernel<<<(n + 7) / 8, 256>>>(b2, out, n);
}

// round 15
// speedup vs baseline: 2.3618x; 1.0117x over previous
#include <cuda_runtime.h>
#include <cuda_fp16.h>
#include <cstdint>
#include <math.h>

#define MAXN 50000
#define MAXE 1000000
#define F1 128
#define F2 16

typedef unsigned long long ull;
typedef unsigned int u32;

// ---------------- device scratch ----------------
__device__ __align__(256) float  g_dinv[MAXN];
__device__ __align__(256) __half g_h1s [MAXN * F1];  // fp16: raw x@W1 (no dinv)
__device__ __align__(256) __half g_h2s [MAXN * F2];  // fp16: dinv*(relu@W2)
__device__ __align__(256) int    g_deg_i[MAXN];
__device__ __align__(256) int    g_cursor[MAXN];
__device__ __align__(256) int    g_row_ptr[MAXN + 1];
__device__ __align__(256) int2   g_csr_sd[MAXE];     // {src, bits(dinv[src])}
__device__ __align__(256) int    g_bsum[64];
__device__ int g_is64;

// ---------------- helpers ----------------
__device__ __forceinline__ long long load_idx(const void* ei, long long i, int is64) {
    if (is64) return ((const long long*)ei)[i];
    return (long long)((const int*)ei)[i];
}
__device__ __forceinline__ void fma2(ull& d, ull a, ull b) {
    asm("fma.rn.f32x2 %0, %1, %2, %3;" : "=l"(d) : "l"(a), "l"(b), "l"(d));
}
__device__ __forceinline__ float unpack_sum(ull v) {
    float lo, hi;
    asm("mov.b64 {%0,%1}, %2;" : "=f"(lo), "=f"(hi) : "l"(v));
    return lo + hi;
}
__device__ __forceinline__ u32 smem_u32(const void* p) {
    return (u32)__cvta_generic_to_shared(p);
}
__device__ __forceinline__ u32 swA(u32 r, u32 b) {
    return r * 128u + ((((b >> 4) ^ (r & 7u)) << 4) | (b & 15u));
}
__device__ __forceinline__ u32 swB(u32 r, u32 b) {
    return r * 256u + ((((b >> 4) ^ (r & 7u)) << 4) | (b & 15u));
}
__device__ __forceinline__ void ldsm4(u32& r0, u32& r1, u32& r2, u32& r3, u32 addr) {
    asm volatile("ldmatrix.sync.aligned.m8n8.x4.shared.b16 {%0,%1,%2,%3}, [%4];"
                 : "=r"(r0), "=r"(r1), "=r"(r2), "=r"(r3) : "r"(addr));
}
__device__ __forceinline__ void ldsm4t(u32& r0, u32& r1, u32& r2, u32& r3, u32 addr) {
    asm volatile("ldmatrix.sync.aligned.m8n8.x4.trans.shared.b16 {%0,%1,%2,%3}, [%4];"
                 : "=r"(r0), "=r"(r1), "=r"(r2), "=r"(r3) : "r"(addr));
}
__device__ __forceinline__ void mma16816(float* c, u32 a0, u32 a1, u32 a2, u32 a3,
                                         u32 b0, u32 b1) {
    asm volatile("mma.sync.aligned.m16n8k16.row.col.f32.f16.f16.f32 "
                 "{%0,%1,%2,%3}, {%4,%5,%6,%7}, {%8,%9}, {%0,%1,%2,%3};"
                 : "+f"(c[0]), "+f"(c[1]), "+f"(c[2]), "+f"(c[3])
                 : "r"(a0), "r"(a1), "r"(a2), "r"(a3), "r"(b0), "r"(b1));
}

// One edge: gather 8 fp16 features, scale by d, accumulate into one set.
__device__ __forceinline__ void edge_acc(const __half* h1, int s, float d, int ln,
                                         float2& p0, float2& p1,
                                         float2& p2, float2& p3) {
    uint4 v = *(const uint4*)&h1[(long long)s * 128 + ln * 8];
    float2 f;
    f = __half22float2(*(__half2*)&v.x);
    p0.x = fmaf(d, f.x, p0.x); p0.y = fmaf(d, f.y, p0.y);
    f = __half22float2(*(__half2*)&v.y);
    p1.x = fmaf(d, f.x, p1.x); p1.y = fmaf(d, f.y, p1.y);
    f = __half22float2(*(__half2*)&v.z);
    p2.x = fmaf(d, f.x, p2.x); p2.y = fmaf(d, f.y, p2.y);
    f = __half22float2(*(__half2*)&v.w);
    p3.x = fmaf(d, f.x, p3.x); p3.y = fmaf(d, f.y, p3.y);
}

// ---------------- kernels ----------------

__global__ void zero_detect_kernel(const void* ei, int n) {
    int i = blockIdx.x * blockDim.x + threadIdx.x;
    if (i < n) { g_deg_i[i] = 0; g_cursor[i] = 0; }
    if (blockIdx.x == 0 && threadIdx.x == 0) {
        const long long* p = (const long long*)ei;
        int ok = 1;
        for (int k = 0; k < 8; k++) {
            long long v = p[k];
            if (v < 0 || v >= n) ok = 0;
        }
        g_is64 = ok;
    }
}

__global__ void deg_kernel(const void* ei, long long E) {
    long long i = (long long)blockIdx.x * blockDim.x + threadIdx.x;
    if (i >= E) return;
    int d = (int)load_idx(ei, E + i, g_is64);
    atomicAdd(&g_deg_i[d], 1);
}

__global__ void scan1_kernel(int n) {
    __shared__ int wsum[32];
    __shared__ int wexcl[32];
    const int tid = threadIdx.x, lane = tid & 31, wid = tid >> 5;
    int i = blockIdx.x * 1024 + tid;
    int d = (i < n) ? g_deg_i[i] : 0;
    int incl = d;
#pragma unroll
    for (int off = 1; off < 32; off <<= 1) {
        int t = __shfl_up_sync(0xffffffffu, incl, off);
        if (lane >= off) incl += t;
    }
    if (lane == 31) wsum[wid] = incl;
    __syncthreads();
    if (wid == 0) {
        int v = wsum[lane];
        int iv = v;
#pragma unroll
        for (int off = 1; off < 32; off <<= 1) {
            int t = __shfl_up_sync(0xffffffffu, iv, off);
            if (lane >= off) iv += t;
        }
        wexcl[lane] = iv - v;
    }
    __syncthreads();
    if (i < n) g_row_ptr[i] = wexcl[wid] + incl - d;
    if (tid == 1023) g_bsum[blockIdx.x] = wexcl[31] + incl;
}

__global__ void scan2_kernel(int n, int nblocks) {
    __shared__ int offset_s;
    const int tid = threadIdx.x;
    if (tid < 32) {
        int acc = 0;
        for (int j = tid; j < blockIdx.x; j += 32) acc += g_bsum[j];
#pragma unroll
        for (int off = 16; off >= 1; off >>= 1)
            acc += __shfl_xor_sync(0xffffffffu, acc, off);
        if (tid == 0) offset_s = acc;
    }
    __syncthreads();
    int i = blockIdx.x * 1024 + tid;
    if (i < n) {
        g_row_ptr[i] += offset_s;
        int d = g_deg_i[i];
        g_dinv[i] = rsqrtf((float)(d > 0 ? d : 1));
    }
    if ((int)blockIdx.x == nblocks - 1 && tid == 0)
        g_row_ptr[n] = offset_s + g_bsum[blockIdx.x];
}

__global__ void fill_kernel(const void* ei, long long E) {
    long long i = (long long)blockIdx.x * blockDim.x + threadIdx.x;
    if (i >= E) return;
    int is64 = g_is64;
    int s = (int)load_idx(ei, i, is64);
    int d = (int)load_idx(ei, E + i, is64);
    int p = atomicAdd(&g_cursor[d], 1);
    g_csr_sd[g_row_ptr[d] + p] = make_int2(s, __float_as_int(g_dinv[s]));
}

// h1s = fp16(x @ W1) via HMMA.
__global__ void __launch_bounds__(256, 2)
gemm1_kernel(const float* __restrict__ x, const float* __restrict__ W1, int n) {
    __shared__ __half As[128 * 64];
    __shared__ __half Bs[64 * 128];
    const int tid = threadIdx.x;
    const int warp = tid >> 5;
    const int lane = tid & 31;
    const int wm = warp >> 2;
    const int wn = warp & 3;
    const int row0 = blockIdx.x * 128;
    const u32 AsB = smem_u32(As);
    const u32 BsB = smem_u32(Bs);

    float acc[4][4][4];
#pragma unroll
    for (int mt = 0; mt < 4; mt++)
#pragma unroll
        for (int nt = 0; nt < 4; nt++)
#pragma unroll
            for (int q = 0; q < 4; q++) acc[mt][nt][q] = 0.f;

    const int sub = lane >> 3, rin = lane & 7;

#pragma unroll
    for (int kc = 0; kc < 2; kc++) {
#pragma unroll
        for (int i = tid; i < 2048; i += 256) {
            int r = i >> 4, c4 = i & 15;
            int grow = row0 + r;
            float4 v = make_float4(0.f, 0.f, 0.f, 0.f);
            if (grow < n)
                v = *(const float4*)&x[(long long)grow * 128 + kc * 64 + c4 * 4];
            __half2 h01 = __floats2half2_rn(v.x, v.y);
            __half2 h23 = __floats2half2_rn(v.z, v.w);
            u32 off = swA(r, c4 * 8);
            *(__half2*)((char*)As + off)     = h01;
            *(__half2*)((char*)As + off + 4) = h23;
        }
#pragma unroll
        for (int i = tid; i < 2048; i += 256) {
            int r = i >> 5, c4 = i & 31;
            float4 v = *(const float4*)&W1[(long long)(kc * 64 + r) * 128 + c4 * 4];
            __half2 h01 = __floats2half2_rn(v.x, v.y);
            __half2 h23 = __floats2half2_rn(v.z, v.w);
            u32 off = swB(r, c4 * 8);
            *(__half2*)((char*)Bs + off)     = h01;
            *(__half2*)((char*)Bs + off + 4) = h23;
        }
        __syncthreads();

#pragma unroll
        for (int kk = 0; kk < 4; kk++) {
            u32 af[4][4];
#pragma unroll
            for (int mt = 0; mt < 4; mt++) {
                u32 r = wm * 64 + mt * 16 + (sub & 1) * 8 + rin;
                u32 bcol = (kk * 16 + (sub >> 1) * 8) * 2;
                ldsm4(af[mt][0], af[mt][1], af[mt][2], af[mt][3], AsB + swA(r, bcol));
            }
            u32 bf[4][2];
#pragma unroll
            for (int ntp = 0; ntp < 2; ntp++) {
                u32 kr = kk * 16 + (sub & 1) * 8 + rin;
                u32 bcol = (wn * 32 + ntp * 16 + (sub >> 1) * 8) * 2;
                u32 r0, r1, r2, r3;
                ldsm4t(r0, r1, r2, r3, BsB + swB(kr, bcol));
                bf[ntp * 2][0] = r0; bf[ntp * 2][1] = r1;
                bf[ntp * 2 + 1][0] = r2; bf[ntp * 2 + 1][1] = r3;
            }
#pragma unroll
            for (int mt = 0; mt < 4; mt++)
#pragma unroll
                for (int nt = 0; nt < 4; nt++)
                    mma16816(acc[mt][nt], af[mt][0], af[mt][1], af[mt][2], af[mt][3],
                             bf[nt][0], bf[nt][1]);
        }
        __syncthreads();
    }

    const int g = lane >> 2, tg = lane & 3;
#pragma unroll
    for (int mt = 0; mt < 4; mt++) {
        int r0g = row0 + wm * 64 + mt * 16 + g;
#pragma unroll
        for (int nt = 0; nt < 4; nt++) {
            int col = wn * 32 + nt * 8 + tg * 2;
            if (r0g < n)
                *(__half2*)&g_h1s[(long long)r0g * 128 + col] =
                    __floats2half2_rn(acc[mt][nt][0], acc[mt][nt][1]);
            if (r0g + 8 < n)
                *(__half2*)&g_h1s[(long long)(r0g + 8) * 128 + col] =
                    __floats2half2_rn(acc[mt][nt][2], acc[mt][nt][3]);
        }
    }
}

// node1: block of 128 threads owns 16 nodes. The block's contiguous CSR slice
// is staged to smem once (coalesced); half-warp per node then loops edges with
// LDS-broadcast indices and 4 independent LDG.128 gathers in flight.
#define NPB 16
#define ESTAGE 1088
__global__ void node1_kernel(const float* __restrict__ b1,
                             const float* __restrict__ W2, int n) {
    __shared__ float W2p[64 * 32];          // [kp][j][2]
    __shared__ float Sa[8][132];            // per half-warp row
    __shared__ int2  Es[ESTAGE];
    const int tid = threadIdx.x;
    const int hw = tid >> 4;                // 0..7
    const int ln = tid & 15;
    const unsigned hmask = 0xFFFFu << (((tid >> 4) & 1) * 16);

    for (int i = tid; i < 2048; i += 128) {
        int k = i >> 4, j = i & 15;
        W2p[(k >> 1) * 32 + j * 2 + (k & 1)] = W2[i];
    }
    float4 blo = *(const float4*)&b1[ln * 8];
    float4 bhi = *(const float4*)&b1[ln * 8 + 4];

    const __half* h1 = g_h1s;
    int node0 = blockIdx.x * NPB;
    int nend = node0 + NPB; if (nend > n) nend = n;
    int gbeg = g_row_ptr[node0];
    int gend = g_row_ptr[nend];
    int m = gend - gbeg;
    bool staged = (m <= ESTAGE);
    if (staged) {
        for (int i = tid; i < m; i += 128) Es[i] = g_csr_sd[gbeg + i];
    }
    __syncthreads();

#pragma unroll 1
    for (int pass = 0; pass < 2; pass++) {
        int node = node0 + pass * 8 + hw;
        if (node < n) {
            int beg = g_row_ptr[node];
            int end = g_row_ptr[node + 1];
            float2 pA0 = make_float2(0.f,0.f), pA1 = pA0, pA2 = pA0, pA3 = pA0;
            float2 pB0 = pA0, pB1 = pA0, pB2 = pA0, pB3 = pA0;
            float2 pC0 = pA0, pC1 = pA0, pC2 = pA0, pC3 = pA0;
            float2 pD0 = pA0, pD1 = pA0, pD2 = pA0, pD3 = pA0;
            if (staged) {
                int e = beg - gbeg, le = end - gbeg;
                for (; e + 4 <= le; e += 4) {
                    int2 e0 = Es[e],     e1 = Es[e + 1];
                    int2 e2 = Es[e + 2], e3 = Es[e + 3];
                    edge_acc(h1, e0.x, __int_as_float(e0.y), ln, pA0, pA1, pA2, pA3);
                    edge_acc(h1, e1.x, __int_as_float(e1.y), ln, pB0, pB1, pB2, pB3);
                    edge_acc(h1, e2.x, __int_as_float(e2.y), ln, pC0, pC1, pC2, pC3);
                    edge_acc(h1, e3.x, __int_as_float(e3.y), ln, pD0, pD1, pD2, pD3);
                }
                for (; e < le; e++) {
                    int2 e0 = Es[e];
                    edge_acc(h1, e0.x, __int_as_float(e0.y), ln, pA0, pA1, pA2, pA3);
                }
            } else {
                int e = beg;
                for (; e + 4 <= end; e += 4) {
                    int2 e0 = g_csr_sd[e],     e1 = g_csr_sd[e + 1];
                    int2 e2 = g_csr_sd[e + 2], e3 = g_csr_sd[e + 3];
                    edge_acc(h1, e0.x, __int_as_float(e0.y), ln, pA0, pA1, pA2, pA3);
                    edge_acc(h1, e1.x, __int_as_float(e1.y), ln, pB0, pB1, pB2, pB3);
                    edge_acc(h1, e2.x, __int_as_float(e2.y), ln, pC0, pC1, pC2, pC3);
                    edge_acc(h1, e3.x, __int_as_float(e3.y), ln, pD0, pD1, pD2, pD3);
                }
                for (; e < end; e++) {
                    int2 e0 = g_csr_sd[e];
                    edge_acc(h1, e0.x, __int_as_float(e0.y), ln, pA0, pA1, pA2, pA3);
                }
            }
            float dv = g_dinv[node];
            float4 s0, s1;
            s0.x = fmaxf(fmaf(dv, (pA0.x + pB0.x) + (pC0.x + pD0.x), blo.x), 0.f);
            s0.y = fmaxf(fmaf(dv, (pA0.y + pB0.y) + (pC0.y + pD0.y), blo.y), 0.f);
            s0.z = fmaxf(fmaf(dv, (pA1.x + pB1.x) + (pC1.x + pD1.x), blo.z), 0.f);
            s0.w = fmaxf(fmaf(dv, (pA1.y + pB1.y) + (pC1.y + pD1.y), blo.w), 0.f);
            s1.x = fmaxf(fmaf(dv, (pA2.x + pB2.x) + (pC2.x + pD2.x), bhi.x), 0.f);
            s1.y = fmaxf(fmaf(dv, (pA2.y + pB2.y) + (pC2.y + pD2.y), bhi.y), 0.f);
            s1.z = fmaxf(fmaf(dv, (pA3.x + pB3.x) + (pC3.x + pD3.x), bhi.z), 0.f);
            s1.w = fmaxf(fmaf(dv, (pA3.y + pB3.y) + (pC3.y + pD3.y), bhi.w), 0.f);
            *(float4*)&Sa[hw][ln * 8]     = s0;
            *(float4*)&Sa[hw][ln * 8 + 4] = s1;
            __syncwarp(hmask);
            ull acc2 = 0ull;
#pragma unroll
            for (int kp = 0; kp < 64; kp++) {
                ull a = *(const ull*)&Sa[hw][2 * kp];
                ull w = *(const ull*)&W2p[kp * 32 + ln * 2];
                fma2(acc2, a, w);
            }
            g_h2s[(long long)node * 16 + ln] = __float2half(unpack_sum(acc2) * dv);
            __syncwarp(hmask);
        }
    }
}

// Warp per node. lane = eo*8 + fp: 4 edges in flight, fp = feature-pair.
__global__ void node2_kernel(const float* __restrict__ b2,
                             float* __restrict__ out, int n) {
    int warpInBlock = threadIdx.x >> 5;
    int lane = threadIdx.x & 31;
    int node = blockIdx.x * (blockDim.x >> 5) + warpInBlock;
    if (node >= n) return;
    const unsigned FULL = 0xffffffffu;
    int eo = lane >> 3;
    int fp = lane & 7;
    int beg = g_row_ptr[node];
    int end = g_row_ptr[node + 1];
    float2 acc = make_float2(0.f, 0.f);
    for (int e = beg + eo; e < end; e += 4) {
        int s = g_csr_sd[e].x;
        float2 f = __half22float2(*(const __half2*)&g_h2s[(long long)s * 16 + 2 * fp]);
        acc.x += f.x; acc.y += f.y;
    }
    acc.x += __shfl_xor_sync(FULL, acc.x, 8);
    acc.y += __shfl_xor_sync(FULL, acc.y, 8);
    acc.x += __shfl_xor_sync(FULL, acc.x, 16);
    acc.y += __shfl_xor_sync(FULL, acc.y, 16);
    float dv = g_dinv[node];
    float2 b = *(const float2*)&b2[2 * fp];
    float vx = fmaf(dv, acc.x, b.x);
    float vy = fmaf(dv, acc.y, b.y);
    float mx = fmaxf(vx, vy);
#pragma unroll
    for (int off = 4; off >= 1; off >>= 1)
        mx = fmaxf(mx, __shfl_xor_sync(FULL, mx, off));
    float ex = expf(vx - mx) + expf(vy - mx);
#pragma unroll
    for (int off = 4; off >= 1; off >>= 1)
        ex += __shfl_xor_sync(FULL, ex, off);
    float lse = mx + logf(ex);
    if (lane < 8) {
        float2 o = make_float2(vx - lse, vy - lse);
        *(float2*)&out[(long long)node * 16 + 2 * fp] = o;
    }
}

// ---------------- launch ----------------
extern "C" void kernel_launch(void* const* d_in, const int* in_sizes, int n_in,
                              void* d_out, int out_size) {
    const float* x  = (const float*)d_in[0];
    const void*  ei = d_in[1];
    const float* W1 = (const float*)d_in[2];
    const float* b1 = (const float*)d_in[3];
    const float* W2 = (const float*)d_in[4];
    const float* b2 = (const float*)d_in[5];
    float* out = (float*)d_out;

    long long E = (long long)in_sizes[1] / 2;
    int n = in_sizes[0] / F1;
    int nScanBlocks = (n + 1023) / 1024;

    static cudaStream_t s2 = nullptr;
    static cudaEvent_t evFork = nullptr, evJoin = nullptr;
    if (!s2) {
        cudaStreamCreateWithFlags(&s2, cudaStreamNonBlocking);
        cudaEventCreateWithFlags(&evFork, cudaEventDisableTiming);
        cudaEventCreateWithFlags(&evJoin, cudaEventDisableTiming);
    }

    cudaEventRecord(evFork, 0);
    cudaStreamWaitEvent(s2, evFork, 0);
    gemm1_kernel<<<(n + 127) / 128, 256, 0, s2>>>(x, W1, n);
    cudaEventRecord(evJoin, s2);

    zero_detect_kernel<<<(n + 255) / 256, 256>>>(ei, n);
    deg_kernel<<<(int)((E + 255) / 256), 256>>>(ei, E);
    scan1_kernel<<<nScanBlocks, 1024>>>(n);
    scan2_kernel<<<nScanBlocks, 1024>>>(n, nScanBlocks);
    fill_kernel<<<(int)((E + 255) / 256), 256>>>(ei, E);

    cudaStreamWaitEvent(0, evJoin, 0);
    node1_kernel<<<(n + NPB - 1) / NPB, 128>>>(b1, W2, n);
    node2_kernel<<<(n + 7) / 8, 256>>>(b2, out, n);
}

// round 16
// speedup vs baseline: 2.3942x; 1.0137x over previous
#include <cuda_runtime.h>
#include <cuda_fp16.h>
#include <cstdint>
#include <math.h>

#define MAXN 50000
#define MAXE 1000000
#define F1 128
#define F2 16

typedef unsigned long long ull;
typedef unsigned int u32;

// ---------------- device scratch ----------------
__device__ __align__(256) float  g_dinv[MAXN];
__device__ __align__(256) __half g_h1s [MAXN * F1];  // fp16: raw x@W1 (no dinv)
__device__ __align__(256) __half g_h2s [MAXN * F2];  // fp16: dinv*(relu@W2)
__device__ __align__(256) int    g_deg_i[MAXN];      // zeroed at end of node2
__device__ __align__(256) int    g_cursor[MAXN];     // zeroed in scan
__device__ __align__(256) int    g_row_ptr[MAXN + 1];
__device__ __align__(256) int2   g_csr_sd[MAXE];     // {src, bits(dinv[src])}
__device__ __align__(256) int    g_bsum[64];
__device__ __align__(256) int    g_flag[64];         // zeroed in deg

// ---------------- helpers ----------------
__device__ __forceinline__ long long load_idx(const void* ei, long long i, int is64) {
    if (is64) return ((const long long*)ei)[i];
    return (long long)((const int*)ei)[i];
}
// Per-block edge-width detection (int64 jax default vs int32 x64-off).
__device__ __forceinline__ int block_detect(const void* ei, int n) {
    __shared__ int s_is64;
    if (threadIdx.x == 0) {
        const long long* p = (const long long*)ei;
        int ok = 1;
#pragma unroll
        for (int k = 0; k < 8; k++) {
            long long v = p[k];
            if (v < 0 || v >= n) ok = 0;
        }
        s_is64 = ok;
    }
    __syncthreads();
    return s_is64;
}
__device__ __forceinline__ void fma2(ull& d, ull a, ull b) {
    asm("fma.rn.f32x2 %0, %1, %2, %3;" : "=l"(d) : "l"(a), "l"(b), "l"(d));
}
__device__ __forceinline__ float unpack_sum(ull v) {
    float lo, hi;
    asm("mov.b64 {%0,%1}, %2;" : "=f"(lo), "=f"(hi) : "l"(v));
    return lo + hi;
}
__device__ __forceinline__ u32 smem_u32(const void* p) {
    return (u32)__cvta_generic_to_shared(p);
}
__device__ __forceinline__ u32 swA(u32 r, u32 b) {
    return r * 128u + ((((b >> 4) ^ (r & 7u)) << 4) | (b & 15u));
}
__device__ __forceinline__ u32 swB(u32 r, u32 b) {
    return r * 256u + ((((b >> 4) ^ (r & 7u)) << 4) | (b & 15u));
}
__device__ __forceinline__ void ldsm4(u32& r0, u32& r1, u32& r2, u32& r3, u32 addr) {
    asm volatile("ldmatrix.sync.aligned.m8n8.x4.shared.b16 {%0,%1,%2,%3}, [%4];"
                 : "=r"(r0), "=r"(r1), "=r"(r2), "=r"(r3) : "r"(addr));
}
__device__ __forceinline__ void ldsm4t(u32& r0, u32& r1, u32& r2, u32& r3, u32 addr) {
    asm volatile("ldmatrix.sync.aligned.m8n8.x4.trans.shared.b16 {%0,%1,%2,%3}, [%4];"
                 : "=r"(r0), "=r"(r1), "=r"(r2), "=r"(r3) : "r"(addr));
}
__device__ __forceinline__ void mma16816(float* c, u32 a0, u32 a1, u32 a2, u32 a3,
                                         u32 b0, u32 b1) {
    asm volatile("mma.sync.aligned.m16n8k16.row.col.f32.f16.f16.f32 "
                 "{%0,%1,%2,%3}, {%4,%5,%6,%7}, {%8,%9}, {%0,%1,%2,%3};"
                 : "+f"(c[0]), "+f"(c[1]), "+f"(c[2]), "+f"(c[3])
                 : "r"(a0), "r"(a1), "r"(a2), "r"(a3), "r"(b0), "r"(b1));
}

// One edge: gather 8 fp16 features, scale by d, accumulate into one set.
__device__ __forceinline__ void edge_acc(const __half* h1, int s, float d, int ln,
                                         float2& p0, float2& p1,
                                         float2& p2, float2& p3) {
    uint4 v = *(const uint4*)&h1[(long long)s * 128 + ln * 8];
    float2 f;
    f = __half22float2(*(__half2*)&v.x);
    p0.x = fmaf(d, f.x, p0.x); p0.y = fmaf(d, f.y, p0.y);
    f = __half22float2(*(__half2*)&v.y);
    p1.x = fmaf(d, f.x, p1.x); p1.y = fmaf(d, f.y, p1.y);
    f = __half22float2(*(__half2*)&v.z);
    p2.x = fmaf(d, f.x, p2.x); p2.y = fmaf(d, f.y, p2.y);
    f = __half22float2(*(__half2*)&v.w);
    p3.x = fmaf(d, f.x, p3.x); p3.y = fmaf(d, f.y, p3.y);
}

// ---------------- kernels ----------------

// deg: histogram dst. Also re-zeroes the scan flags for this run.
__global__ void deg_kernel(const void* ei, long long E, int n) {
    int is64 = block_detect(ei, n);
    long long i = (long long)blockIdx.x * blockDim.x + threadIdx.x;
    if (blockIdx.x == 0 && threadIdx.x < 64) g_flag[threadIdx.x] = 0;
    if (i >= E) return;
    int d = (int)load_idx(ei, E + i, is64);
    atomicAdd(&g_deg_i[d], 1);
}

// Fused scan (decoupled lookback, 49 blocks all resident) + dinv + cursor=0.
__global__ void scan_kernel(int n, int nblocks) {
    __shared__ int wsum[32];
    __shared__ int wexcl[32];
    __shared__ int offset_s;
    const int tid = threadIdx.x, lane = tid & 31, wid = tid >> 5;
    const int bid = blockIdx.x;
    int i = bid * 1024 + tid;
    int d = (i < n) ? g_deg_i[i] : 0;
    int incl = d;
#pragma unroll
    for (int off = 1; off < 32; off <<= 1) {
        int t = __shfl_up_sync(0xffffffffu, incl, off);
        if (lane >= off) incl += t;
    }
    if (lane == 31) wsum[wid] = incl;
    __syncthreads();
    if (wid == 0) {
        int v = wsum[lane];
        int iv = v;
#pragma unroll
        for (int off = 1; off < 32; off <<= 1) {
            int t = __shfl_up_sync(0xffffffffu, iv, off);
            if (lane >= off) iv += t;
        }
        wexcl[lane] = iv - v;
    }
    __syncthreads();
    int blockTotal = wexcl[31] + wsum[31];
    // publish this block's total
    if (tid == 0) {
        g_bsum[bid] = blockTotal;
        __threadfence();
        atomicExch(&g_flag[bid], 1);
    }
    // lookback: warp 0 sums predecessor totals
    if (tid < 32) {
        int acc = 0;
        for (int j = tid; j < bid; j += 32) {
            while (atomicAdd(&g_flag[j], 0) == 0) { }
            acc += g_bsum[j];
        }
#pragma unroll
        for (int off = 16; off >= 1; off >>= 1)
            acc += __shfl_xor_sync(0xffffffffu, acc, off);
        if (tid == 0) offset_s = acc;
    }
    __syncthreads();
    if (i < n) {
        g_row_ptr[i] = offset_s + wexcl[wid] + incl - d;
        g_dinv[i] = rsqrtf((float)(d > 0 ? d : 1));
        g_cursor[i] = 0;
    }
    if (bid == nblocks - 1 && tid == 0)
        g_row_ptr[n] = offset_s + blockTotal;
}

__global__ void fill_kernel(const void* ei, long long E, int n) {
    int is64 = block_detect(ei, n);
    long long i = (long long)blockIdx.x * blockDim.x + threadIdx.x;
    if (i >= E) return;
    int s = (int)load_idx(ei, i, is64);
    int d = (int)load_idx(ei, E + i, is64);
    int p = atomicAdd(&g_cursor[d], 1);
    g_csr_sd[g_row_ptr[d] + p] = make_int2(s, __float_as_int(g_dinv[s]));
}

// h1s = fp16(x @ W1) via HMMA.
__global__ void __launch_bounds__(256, 2)
gemm1_kernel(const float* __restrict__ x, const float* __restrict__ W1, int n) {
    __shared__ __half As[128 * 64];
    __shared__ __half Bs[64 * 128];
    const int tid = threadIdx.x;
    const int warp = tid >> 5;
    const int lane = tid & 31;
    const int wm = warp >> 2;
    const int wn = warp & 3;
    const int row0 = blockIdx.x * 128;
    const u32 AsB = smem_u32(As);
    const u32 BsB = smem_u32(Bs);

    float acc[4][4][4];
#pragma unroll
    for (int mt = 0; mt < 4; mt++)
#pragma unroll
        for (int nt = 0; nt < 4; nt++)
#pragma unroll
            for (int q = 0; q < 4; q++) acc[mt][nt][q] = 0.f;

    const int sub = lane >> 3, rin = lane & 7;

#pragma unroll
    for (int kc = 0; kc < 2; kc++) {
#pragma unroll
        for (int i = tid; i < 2048; i += 256) {
            int r = i >> 4, c4 = i & 15;
            int grow = row0 + r;
            float4 v = make_float4(0.f, 0.f, 0.f, 0.f);
            if (grow < n)
                v = *(const float4*)&x[(long long)grow * 128 + kc * 64 + c4 * 4];
            __half2 h01 = __floats2half2_rn(v.x, v.y);
            __half2 h23 = __floats2half2_rn(v.z, v.w);
            u32 off = swA(r, c4 * 8);
            *(__half2*)((char*)As + off)     = h01;
            *(__half2*)((char*)As + off + 4) = h23;
        }
#pragma unroll
        for (int i = tid; i < 2048; i += 256) {
            int r = i >> 5, c4 = i & 31;
            float4 v = *(const float4*)&W1[(long long)(kc * 64 + r) * 128 + c4 * 4];
            __half2 h01 = __floats2half2_rn(v.x, v.y);
            __half2 h23 = __floats2half2_rn(v.z, v.w);
            u32 off = swB(r, c4 * 8);
            *(__half2*)((char*)Bs + off)     = h01;
            *(__half2*)((char*)Bs + off + 4) = h23;
        }
        __syncthreads();

#pragma unroll
        for (int kk = 0; kk < 4; kk++) {
            u32 af[4][4];
#pragma unroll
            for (int mt = 0; mt < 4; mt++) {
                u32 r = wm * 64 + mt * 16 + (sub & 1) * 8 + rin;
                u32 bcol = (kk * 16 + (sub >> 1) * 8) * 2;
                ldsm4(af[mt][0], af[mt][1], af[mt][2], af[mt][3], AsB + swA(r, bcol));
            }
            u32 bf[4][2];
#pragma unroll
            for (int ntp = 0; ntp < 2; ntp++) {
                u32 kr = kk * 16 + (sub & 1) * 8 + rin;
                u32 bcol = (wn * 32 + ntp * 16 + (sub >> 1) * 8) * 2;
                u32 r0, r1, r2, r3;
                ldsm4t(r0, r1, r2, r3, BsB + swB(kr, bcol));
                bf[ntp * 2][0] = r0; bf[ntp * 2][1] = r1;
                bf[ntp * 2 + 1][0] = r2; bf[ntp * 2 + 1][1] = r3;
            }
#pragma unroll
            for (int mt = 0; mt < 4; mt++)
#pragma unroll
                for (int nt = 0; nt < 4; nt++)
                    mma16816(acc[mt][nt], af[mt][0], af[mt][1], af[mt][2], af[mt][3],
                             bf[nt][0], bf[nt][1]);
        }
        __syncthreads();
    }

    const int g = lane >> 2, tg = lane & 3;
#pragma unroll
    for (int mt = 0; mt < 4; mt++) {
        int r0g = row0 + wm * 64 + mt * 16 + g;
#pragma unroll
        for (int nt = 0; nt < 4; nt++) {
            int col = wn * 32 + nt * 8 + tg * 2;
            if (r0g < n)
                *(__half2*)&g_h1s[(long long)r0g * 128 + col] =
                    __floats2half2_rn(acc[mt][nt][0], acc[mt][nt][1]);
            if (r0g + 8 < n)
                *(__half2*)&g_h1s[(long long)(r0g + 8) * 128 + col] =
                    __floats2half2_rn(acc[mt][nt][2], acc[mt][nt][3]);
        }
    }
}

// node1: block owns 16 nodes; CSR slice staged to smem; half-warp per node,
// LDG.128 gathers, 4 edges in flight; reduce-free W2 phase.
#define NPB 16
#define ESTAGE 1088
__global__ void node1_kernel(const float* __restrict__ b1,
                             const float* __restrict__ W2, int n) {
    __shared__ float W2p[64 * 32];          // [kp][j][2]
    __shared__ float Sa[8][132];            // per half-warp row
    __shared__ int2  Es[ESTAGE];
    const int tid = threadIdx.x;
    const int hw = tid >> 4;                // 0..7
    const int ln = tid & 15;
    const unsigned hmask = 0xFFFFu << (((tid >> 4) & 1) * 16);

    for (int i = tid; i < 2048; i += 128) {
        int k = i >> 4, j = i & 15;
        W2p[(k >> 1) * 32 + j * 2 + (k & 1)] = W2[i];
    }
    float4 blo = *(const float4*)&b1[ln * 8];
    float4 bhi = *(const float4*)&b1[ln * 8 + 4];

    const __half* h1 = g_h1s;
    int node0 = blockIdx.x * NPB;
    int nend = node0 + NPB; if (nend > n) nend = n;
    int gbeg = g_row_ptr[node0];
    int gend = g_row_ptr[nend];
    int m = gend - gbeg;
    bool staged = (m <= ESTAGE);
    if (staged) {
        for (int i = tid; i < m; i += 128) Es[i] = g_csr_sd[gbeg + i];
    }
    __syncthreads();

#pragma unroll 1
    for (int pass = 0; pass < 2; pass++) {
        int node = node0 + pass * 8 + hw;
        if (node < n) {
            int beg = g_row_ptr[node];
            int end = g_row_ptr[node + 1];
            float2 pA0 = make_float2(0.f,0.f), pA1 = pA0, pA2 = pA0, pA3 = pA0;
            float2 pB0 = pA0, pB1 = pA0, pB2 = pA0, pB3 = pA0;
            float2 pC0 = pA0, pC1 = pA0, pC2 = pA0, pC3 = pA0;
            float2 pD0 = pA0, pD1 = pA0, pD2 = pA0, pD3 = pA0;
            if (staged) {
                int e = beg - gbeg, le = end - gbeg;
                for (; e + 4 <= le; e += 4) {
                    int2 e0 = Es[e],     e1 = Es[e + 1];
                    int2 e2 = Es[e + 2], e3 = Es[e + 3];
                    edge_acc(h1, e0.x, __int_as_float(e0.y), ln, pA0, pA1, pA2, pA3);
                    edge_acc(h1, e1.x, __int_as_float(e1.y), ln, pB0, pB1, pB2, pB3);
                    edge_acc(h1, e2.x, __int_as_float(e2.y), ln, pC0, pC1, pC2, pC3);
                    edge_acc(h1, e3.x, __int_as_float(e3.y), ln, pD0, pD1, pD2, pD3);
                }
                for (; e < le; e++) {
                    int2 e0 = Es[e];
                    edge_acc(h1, e0.x, __int_as_float(e0.y), ln, pA0, pA1, pA2, pA3);
                }
            } else {
                int e = beg;
                for (; e + 4 <= end; e += 4) {
                    int2 e0 = g_csr_sd[e],     e1 = g_csr_sd[e + 1];
                    int2 e2 = g_csr_sd[e + 2], e3 = g_csr_sd[e + 3];
                    edge_acc(h1, e0.x, __int_as_float(e0.y), ln, pA0, pA1, pA2, pA3);
                    edge_acc(h1, e1.x, __int_as_float(e1.y), ln, pB0, pB1, pB2, pB3);
                    edge_acc(h1, e2.x, __int_as_float(e2.y), ln, pC0, pC1, pC2, pC3);
                    edge_acc(h1, e3.x, __int_as_float(e3.y), ln, pD0, pD1, pD2, pD3);
                }
                for (; e < end; e++) {
                    int2 e0 = g_csr_sd[e];
                    edge_acc(h1, e0.x, __int_as_float(e0.y), ln, pA0, pA1, pA2, pA3);
                }
            }
            float dv = g_dinv[node];
            float4 s0, s1;
            s0.x = fmaxf(fmaf(dv, (pA0.x + pB0.x) + (pC0.x + pD0.x), blo.x), 0.f);
            s0.y = fmaxf(fmaf(dv, (pA0.y + pB0.y) + (pC0.y + pD0.y), blo.y), 0.f);
            s0.z = fmaxf(fmaf(dv, (pA1.x + pB1.x) + (pC1.x + pD1.x), blo.z), 0.f);
            s0.w = fmaxf(fmaf(dv, (pA1.y + pB1.y) + (pC1.y + pD1.y), blo.w), 0.f);
            s1.x = fmaxf(fmaf(dv, (pA2.x + pB2.x) + (pC2.x + pD2.x), bhi.x), 0.f);
            s1.y = fmaxf(fmaf(dv, (pA2.y + pB2.y) + (pC2.y + pD2.y), bhi.y), 0.f);
            s1.z = fmaxf(fmaf(dv, (pA3.x + pB3.x) + (pC3.x + pD3.x), bhi.z), 0.f);
            s1.w = fmaxf(fmaf(dv, (pA3.y + pB3.y) + (pC3.y + pD3.y), bhi.w), 0.f);
            *(float4*)&Sa[hw][ln * 8]     = s0;
            *(float4*)&Sa[hw][ln * 8 + 4] = s1;
            __syncwarp(hmask);
            ull acc2 = 0ull;
#pragma unroll
            for (int kp = 0; kp < 64; kp++) {
                ull a = *(const ull*)&Sa[hw][2 * kp];
                ull w = *(const ull*)&W2p[kp * 32 + ln * 2];
                fma2(acc2, a, w);
            }
            g_h2s[(long long)node * 16 + ln] = __float2half(unpack_sum(acc2) * dv);
            __syncwarp(hmask);
        }
    }
}

// Warp per node; also re-zeroes g_deg_i for the next run (after its last reader).
__global__ void node2_kernel(const float* __restrict__ b2,
                             float* __restrict__ out, int n) {
    int warpInBlock = threadIdx.x >> 5;
    int lane = threadIdx.x & 31;
    int node = blockIdx.x * (blockDim.x >> 5) + warpInBlock;
    if (node >= n) return;
    const unsigned FULL = 0xffffffffu;
    int eo = lane >> 3;
    int fp = lane & 7;
    int beg = g_row_ptr[node];
    int end = g_row_ptr[node + 1];
    if (lane == 0) g_deg_i[node] = 0;
    float2 acc = make_float2(0.f, 0.f);
    for (int e = beg + eo; e < end; e += 4) {
        int s = g_csr_sd[e].x;
        float2 f = __half22float2(*(const __half2*)&g_h2s[(long long)s * 16 + 2 * fp]);
        acc.x += f.x; acc.y += f.y;
    }
    acc.x += __shfl_xor_sync(FULL, acc.x, 8);
    acc.y += __shfl_xor_sync(FULL, acc.y, 8);
    acc.x += __shfl_xor_sync(FULL, acc.x, 16);
    acc.y += __shfl_xor_sync(FULL, acc.y, 16);
    float dv = g_dinv[node];
    float2 b = *(const float2*)&b2[2 * fp];
    float vx = fmaf(dv, acc.x, b.x);
    float vy = fmaf(dv, acc.y, b.y);
    float mx = fmaxf(vx, vy);
#pragma unroll
    for (int off = 4; off >= 1; off >>= 1)
        mx = fmaxf(mx, __shfl_xor_sync(FULL, mx, off));
    float ex = expf(vx - mx) + expf(vy - mx);
#pragma unroll
    for (int off = 4; off >= 1; off >>= 1)
        ex += __shfl_xor_sync(FULL, ex, off);
    float lse = mx + logf(ex);
    if (lane < 8) {
        float2 o = make_float2(vx - lse, vy - lse);
        *(float2*)&out[(long long)node * 16 + 2 * fp] = o;
    }
}

// ---------------- launch ----------------
extern "C" void kernel_launch(void* const* d_in, const int* in_sizes, int n_in,
                              void* d_out, int out_size) {
    const float* x  = (const float*)d_in[0];
    const void*  ei = d_in[1];
    const float* W1 = (const float*)d_in[2];
    const float* b1 = (const float*)d_in[3];
    const float* W2 = (const float*)d_in[4];
    const float* b2 = (const float*)d_in[5];
    float* out = (float*)d_out;

    long long E = (long long)in_sizes[1] / 2;
    int n = in_sizes[0] / F1;
    int nScanBlocks = (n + 1023) / 1024;

    static cudaStream_t s2 = nullptr;
    static cudaEvent_t evFork = nullptr, evJoin = nullptr;
    if (!s2) {
        cudaStreamCreateWithFlags(&s2, cudaStreamNonBlocking);
        cudaEventCreateWithFlags(&evFork, cudaEventDisableTiming);
        cudaEventCreateWithFlags(&evJoin, cudaEventDisableTiming);
    }

    cudaEventRecord(evFork, 0);
    cudaStreamWaitEvent(s2, evFork, 0);
    gemm1_kernel<<<(n + 127) / 128, 256, 0, s2>>>(x, W1, n);
    cudaEventRecord(evJoin, s2);

    deg_kernel<<<(int)((E + 255) / 256), 256>>>(ei, E, n);
    scan_kernel<<<nScanBlocks, 1024>>>(n, nScanBlocks);
    fill_kernel<<<(int)((E + 255) / 256), 256>>>(ei, E, n);

    cudaStreamWaitEvent(0, evJoin, 0);
    node1_kernel<<<(n + NPB - 1) / NPB, 128>>>(b1, W2, n);
    node2_kernel<<<(n + 7) / 8, 256>>>(b2, out, n);
}